// round 11
// baseline (speedup 1.0000x reference)
#include <cuda_runtime.h>
#include <cuda_fp16.h>
#include <cstdint>

// ---------------------------------------------------------------------------
// GIN block. 8-kernel pipeline:
//   init (dtype detect + zero) -> hist -> single-pass lookback scan ->
//   permute -> aggregate (CSR gather, full occupancy) ->
//   gemm1 (mma.sync 3xFP16-split m16n8k16, fused BN1 stats) ->
//   gemm2 (BN1+ReLU folded on load, fused BN2 stats) -> bnrelu.
// R8 lesson: don't fuse the gather into the 1-CTA/SM GEMM.
// R6 lesson: __device__ symbols only from device code.
// R10 lesson: irregular kernels are ATOMG/L2-latency bound -> widen ILP.
// ---------------------------------------------------------------------------

#define MAXN 50048
#define MAXE 1600000

__device__ __align__(16) float g_agg[MAXN * 128];
__device__ __align__(16) float g_h1[MAXN * 128];
__device__ float g_stats[512];   // [sum1, sumsq1, sum2, sumsq2] x 128
__device__ int   g_deg[MAXN + 1];
__device__ int   g_off[MAXN + 1];
__device__ int   g_pos[MAXN + 1];
__device__ unsigned long long g_look[64];  // lookback: flag(hi32) | value(lo32)
__device__ int   g_srcsorted[MAXE];
__device__ int   g_is64;

// ---------------------------------------------------------------------------
__global__ void init_kernel(const int* __restrict__ ei32, int E, int N) {
    int i = blockIdx.x * blockDim.x + threadIdx.x;
    if (i <= N) g_deg[i] = 0;
    if (i < 512) g_stats[i] = 0.f;
    if (i < 64) g_look[i] = 0ull;
    if (blockIdx.x == 0) {
        __shared__ int nz;
        if (threadIdx.x == 0) nz = 0;
        __syncthreads();
        int pairs = E < 2048 ? E : 2048;
        int cnt = 0;
        for (int j = threadIdx.x; j < pairs; j += blockDim.x)
            if (ei32[2 * j + 1] != 0) cnt++;
        if (cnt) atomicOr(&nz, 1);
        __syncthreads();
        if (threadIdx.x == 0) g_is64 = (nz == 0) ? 1 : 0;
    }
}

__device__ __forceinline__ int load_idx(const void* ei, long long i) {
    return g_is64 ? (int)((const long long*)ei)[i] : ((const int*)ei)[i];
}

// 4 edges per thread: batch loads, then independent atomics.
__global__ void hist_kernel(const void* __restrict__ ei, int E) {
    int i = (blockIdx.x * blockDim.x + threadIdx.x) * 4;
    if (i + 3 < E) {
        int d0 = load_idx(ei, (long long)E + i + 0);
        int d1 = load_idx(ei, (long long)E + i + 1);
        int d2 = load_idx(ei, (long long)E + i + 2);
        int d3 = load_idx(ei, (long long)E + i + 3);
        atomicAdd(&g_deg[d0], 1);
        atomicAdd(&g_deg[d1], 1);
        atomicAdd(&g_deg[d2], 1);
        atomicAdd(&g_deg[d3], 1);
    } else {
        for (; i < E; ++i)
            atomicAdd(&g_deg[load_idx(ei, (long long)E + i)], 1);
    }
}

// Single-pass exclusive scan of g_deg via decoupled lookback (nb <= 49).
__global__ void __launch_bounds__(256) csr_scan(int N, int nb) {
    __shared__ int sh[256];
    __shared__ int sbase;
    int b = blockIdx.x, tid = threadIdx.x;
    int i0 = b * 1024 + tid * 4;
    int d0 = 0, d1 = 0, d2 = 0, d3 = 0;
    if (i0 + 0 < N) d0 = g_deg[i0 + 0];
    if (i0 + 1 < N) d1 = g_deg[i0 + 1];
    if (i0 + 2 < N) d2 = g_deg[i0 + 2];
    if (i0 + 3 < N) d3 = g_deg[i0 + 3];
    int tsum = d0 + d1 + d2 + d3;
    sh[tid] = tsum;
    __syncthreads();
    for (int d = 1; d < 256; d <<= 1) {
        int t = (tid >= d) ? sh[tid - d] : 0;
        __syncthreads();
        sh[tid] += t;
        __syncthreads();
    }
    int agg = sh[255];
    if (tid == 0) {
        if (b == 0) {
            atomicExch(&g_look[0], (2ull << 32) | (unsigned)agg);
            sbase = 0;
        } else {
            atomicExch(&g_look[b], (1ull << 32) | (unsigned)agg);
            int ex = 0;
            int i = b - 1;
            while (true) {
                unsigned long long v;
                do { v = atomicAdd(&g_look[i], 0ull); } while ((v >> 32) == 0ull);
                ex += (int)(unsigned)v;
                if ((v >> 32) == 2ull) break;
                --i;
            }
            atomicExch(&g_look[b], (2ull << 32) | (unsigned)(ex + agg));
            sbase = ex;
        }
    }
    __syncthreads();
    int o0 = sbase + sh[tid] - tsum;
    int o1 = o0 + d0, o2 = o1 + d1, o3 = o2 + d2;
    if (i0 + 0 < N) { g_off[i0 + 0] = o0; g_pos[i0 + 0] = o0; }
    if (i0 + 1 < N) { g_off[i0 + 1] = o1; g_pos[i0 + 1] = o1; }
    if (i0 + 2 < N) { g_off[i0 + 2] = o2; g_pos[i0 + 2] = o2; }
    if (i0 + 3 < N) { g_off[i0 + 3] = o3; g_pos[i0 + 3] = o3; }
    if (b == nb - 1 && tid == 255) g_off[N] = sbase + agg;
}

// 4 edges per thread: load all, then 4 independent atomic->store chains.
__global__ void permute_kernel(const void* __restrict__ ei, int E) {
    int i = (blockIdx.x * blockDim.x + threadIdx.x) * 4;
    if (i + 3 < E) {
        int s0 = load_idx(ei, i + 0);
        int s1 = load_idx(ei, i + 1);
        int s2 = load_idx(ei, i + 2);
        int s3 = load_idx(ei, i + 3);
        int d0 = load_idx(ei, (long long)E + i + 0);
        int d1 = load_idx(ei, (long long)E + i + 1);
        int d2 = load_idx(ei, (long long)E + i + 2);
        int d3 = load_idx(ei, (long long)E + i + 3);
        int p0 = atomicAdd(&g_pos[d0], 1);
        int p1 = atomicAdd(&g_pos[d1], 1);
        int p2 = atomicAdd(&g_pos[d2], 1);
        int p3 = atomicAdd(&g_pos[d3], 1);
        g_srcsorted[p0] = s0;
        g_srcsorted[p1] = s1;
        g_srcsorted[p2] = s2;
        g_srcsorted[p3] = s3;
    } else {
        for (; i < E; ++i) {
            int src = load_idx(ei, i);
            int dst = load_idx(ei, (long long)E + i);
            g_srcsorted[atomicAdd(&g_pos[dst], 1)] = src;
        }
    }
}

// One warp per node: acc = (1+eps)*x[node] + sum of neighbor rows; one store.
// 8-wide gather unroll for deep MLP against L2 latency.
__global__ void aggregate_kernel(const float* __restrict__ x,
                                 const float* __restrict__ eps, int N) {
    int w = (int)((blockIdx.x * blockDim.x + threadIdx.x) >> 5);
    if (w >= N) return;
    int lane = threadIdx.x & 31;
    const float4* x4 = (const float4*)x;
    float s = 1.f + eps[0];
    float4 acc = x4[(size_t)w * 32 + lane];
    acc.x *= s; acc.y *= s; acc.z *= s; acc.w *= s;
    float4 acc2 = make_float4(0.f, 0.f, 0.f, 0.f);
    int j = g_off[w], end = g_off[w + 1];
    for (; j + 7 < end; j += 8) {
        int sidx[8];
#pragma unroll
        for (int t = 0; t < 8; ++t) sidx[t] = g_srcsorted[j + t];
        float4 v[8];
#pragma unroll
        for (int t = 0; t < 8; ++t) v[t] = x4[(size_t)sidx[t] * 32 + lane];
#pragma unroll
        for (int t = 0; t < 8; t += 2) {
            acc.x  += v[t].x;     acc.y  += v[t].y;
            acc.z  += v[t].z;     acc.w  += v[t].w;
            acc2.x += v[t + 1].x; acc2.y += v[t + 1].y;
            acc2.z += v[t + 1].z; acc2.w += v[t + 1].w;
        }
    }
    for (; j + 1 < end; j += 2) {
        int s0 = g_srcsorted[j], s1 = g_srcsorted[j + 1];
        float4 v0 = x4[(size_t)s0 * 32 + lane];
        float4 v1 = x4[(size_t)s1 * 32 + lane];
        acc.x  += v0.x; acc.y  += v0.y; acc.z  += v0.z; acc.w  += v0.w;
        acc2.x += v1.x; acc2.y += v1.y; acc2.z += v1.z; acc2.w += v1.w;
    }
    if (j < end) {
        float4 v0 = x4[(size_t)g_srcsorted[j] * 32 + lane];
        acc.x += v0.x; acc.y += v0.y; acc.z += v0.z; acc.w += v0.w;
    }
    acc.x += acc2.x; acc.y += acc2.y; acc.z += acc2.z; acc.w += acc2.w;
    ((float4*)g_agg)[(size_t)w * 32 + lane] = acc;
}

// ---------------------------------------------------------------------------
// 3xFP16-split tensor-core GEMM (m16n8k16): D = Ain @ W^T + bias.
// x = hi + lo (fp16 each, ~22-bit combined mantissa); D accumulates
// Ahi*Bhi + Ahi*Blo + Alo*Bhi in fp32 (lo*lo ~2^-22 dropped).
// SMEM: Ahi/Alo/Bhi/Blo as fp16x2 words [128 rows][68-word stride].
// CTA: 128x128 tile, 8 warps = 4 row-groups(32) x 2 col-groups(64).
// BN1=false (gemm1): A=g_agg, C=g_h1, stats -> g_stats[0/128].
// BN1=true  (gemm2): A=relu(BN1(g_h1)), C=outp, stats -> g_stats[256/384].
// ---------------------------------------------------------------------------
#define ROWW 68                         // words per row (64 + 4 pad)
#define SMO_AH   0
#define SMO_AL   (128*ROWW*4)           // 34816
#define SMO_BH   (2*128*ROWW*4)         // 69632
#define SMO_BL   (3*128*ROWW*4)         // 104448
#define SMO_BIAS (4*128*ROWW*4)         // 139264
#define SMO_SA   (SMO_BIAS + 512)
#define SMO_SC   (SMO_SA + 512)
#define SMO_SS   (SMO_SC + 512)
#define SMO_SQ   (SMO_SS + 512)
#define SMEM_GEMM (SMO_SQ + 512)        // 141824 bytes

__device__ __forceinline__ void split_h2(float x, float y,
                                         uint32_t& hi, uint32_t& lo) {
    __half hx = __float2half_rn(x), hy = __float2half_rn(y);
    __half lx = __float2half_rn(x - __half2float(hx));
    __half ly = __float2half_rn(y - __half2float(hy));
    hi = (uint32_t)__half_as_ushort(hx) | ((uint32_t)__half_as_ushort(hy) << 16);
    lo = (uint32_t)__half_as_ushort(lx) | ((uint32_t)__half_as_ushort(ly) << 16);
}

__device__ __forceinline__ void mma_f16(float* d, const uint32_t* a,
                                        uint32_t b0, uint32_t b1) {
    asm volatile(
        "mma.sync.aligned.m16n8k16.row.col.f32.f16.f16.f32 "
        "{%0,%1,%2,%3}, {%4,%5,%6,%7}, {%8,%9}, {%0,%1,%2,%3};"
        : "+f"(d[0]), "+f"(d[1]), "+f"(d[2]), "+f"(d[3])
        : "r"(a[0]), "r"(a[1]), "r"(a[2]), "r"(a[3]), "r"(b0), "r"(b1));
}

template <bool BN1>
__global__ void __launch_bounds__(256, 1)
gemm_mma(const float* __restrict__ W, const float* __restrict__ bias,
         const float* __restrict__ gamma, const float* __restrict__ beta,
         float* __restrict__ outp, int N, float invN) {
    const float* A  = BN1 ? g_h1 : g_agg;
    float* C        = BN1 ? outp : g_h1;
    float* statSum  = BN1 ? (g_stats + 256) : g_stats;
    float* statSq   = BN1 ? (g_stats + 384) : (g_stats + 128);

    extern __shared__ __align__(16) char smem[];
    uint32_t* Ah = (uint32_t*)(smem + SMO_AH);
    uint32_t* Al = (uint32_t*)(smem + SMO_AL);
    uint32_t* Bh = (uint32_t*)(smem + SMO_BH);
    uint32_t* Bl = (uint32_t*)(smem + SMO_BL);
    float* sbias = (float*)(smem + SMO_BIAS);
    float* s_a   = (float*)(smem + SMO_SA);
    float* s_c   = (float*)(smem + SMO_SC);
    float* sS    = (float*)(smem + SMO_SS);
    float* sQ    = (float*)(smem + SMO_SQ);

    int tid = threadIdx.x, wid = tid >> 5, lane = tid & 31;
    int wr = wid >> 1;        // 0..3 : rows wr*32 .. +32
    int wc = wid & 1;         // 0..1 : cols wc*64 .. +64
    int gid = lane >> 2;      // 0..7
    int tig = lane & 3;       // 0..3
    int m0 = blockIdx.x * 128;

    if (tid < 128) {
        sbias[tid] = bias[tid];
        sS[tid] = 0.f;
        sQ[tid] = 0.f;
        if (BN1) {
            float mu  = g_stats[tid] * invN;
            float var = g_stats[128 + tid] * invN - mu * mu;
            float a = gamma[tid] * rsqrtf(var + 1e-5f);
            s_a[tid] = a;
            s_c[tid] = beta[tid] - mu * a;
        }
    }
    __syncthreads();

    // ---- load + split A tile ----
#pragma unroll
    for (int it = 0; it < 16; ++it) {
        int idx = tid + it * 256;        // 0..4095
        int row = idx >> 5;              // 0..127
        int kq  = idx & 31;              // float4 index 0..31
        int gm = m0 + row; if (gm >= N) gm = N - 1;
        float4 v = *(const float4*)(A + (size_t)gm * 128 + kq * 4);
        if (BN1) {
            int k0 = kq * 4;
            v.x = fmaxf(fmaf(v.x, s_a[k0 + 0], s_c[k0 + 0]), 0.f);
            v.y = fmaxf(fmaf(v.y, s_a[k0 + 1], s_c[k0 + 1]), 0.f);
            v.z = fmaxf(fmaf(v.z, s_a[k0 + 2], s_c[k0 + 2]), 0.f);
            v.w = fmaxf(fmaf(v.w, s_a[k0 + 3], s_c[k0 + 3]), 0.f);
        }
        uint32_t h0, l0, h1, l1;
        split_h2(v.x, v.y, h0, l0);
        split_h2(v.z, v.w, h1, l1);
        int o = row * ROWW + kq * 2;
        *(uint2*)(Ah + o) = make_uint2(h0, h1);
        *(uint2*)(Al + o) = make_uint2(l0, l1);
    }
    // ---- load + split W ----
#pragma unroll
    for (int it = 0; it < 16; ++it) {
        int idx = tid + it * 256;
        int row = idx >> 5;              // n
        int kq  = idx & 31;
        float4 v = *(const float4*)(W + (size_t)row * 128 + kq * 4);
        uint32_t h0, l0, h1, l1;
        split_h2(v.x, v.y, h0, l0);
        split_h2(v.z, v.w, h1, l1);
        int o = row * ROWW + kq * 2;
        *(uint2*)(Bh + o) = make_uint2(h0, h1);
        *(uint2*)(Bl + o) = make_uint2(l0, l1);
    }
    __syncthreads();

    // ---- mainloop: 8 K-chunks of 16 ----
    float acc[2][8][4];
#pragma unroll
    for (int mt = 0; mt < 2; ++mt)
#pragma unroll
        for (int nt = 0; nt < 8; ++nt)
#pragma unroll
            for (int r = 0; r < 4; ++r) acc[mt][nt][r] = 0.f;

#pragma unroll
    for (int ks = 0; ks < 8; ++ks) {
        int kw0 = ks * 8;  // word offset of this K-chunk
        uint32_t ahi[2][4], alo[2][4];
#pragma unroll
        for (int mt = 0; mt < 2; ++mt) {
            int r0 = wr * 32 + mt * 16 + gid;
            ahi[mt][0] = Ah[r0 * ROWW + kw0 + tig];
            ahi[mt][1] = Ah[(r0 + 8) * ROWW + kw0 + tig];
            ahi[mt][2] = Ah[r0 * ROWW + kw0 + tig + 4];
            ahi[mt][3] = Ah[(r0 + 8) * ROWW + kw0 + tig + 4];
            alo[mt][0] = Al[r0 * ROWW + kw0 + tig];
            alo[mt][1] = Al[(r0 + 8) * ROWW + kw0 + tig];
            alo[mt][2] = Al[r0 * ROWW + kw0 + tig + 4];
            alo[mt][3] = Al[(r0 + 8) * ROWW + kw0 + tig + 4];
        }
#pragma unroll
        for (int nt = 0; nt < 8; ++nt) {
            int n = wc * 64 + nt * 8 + gid;
            uint32_t bh0 = Bh[n * ROWW + kw0 + tig];
            uint32_t bh1 = Bh[n * ROWW + kw0 + tig + 4];
            uint32_t bl0 = Bl[n * ROWW + kw0 + tig];
            uint32_t bl1 = Bl[n * ROWW + kw0 + tig + 4];
#pragma unroll
            for (int mt = 0; mt < 2; ++mt) {
                mma_f16(acc[mt][nt], ahi[mt], bh0, bh1);
                mma_f16(acc[mt][nt], ahi[mt], bl0, bl1);
                mma_f16(acc[mt][nt], alo[mt], bh0, bh1);
            }
        }
    }

    // ---- epilogue: bias add, store, fused column stats ----
    float ls[16], lq[16];
#pragma unroll
    for (int i = 0; i < 16; ++i) { ls[i] = 0.f; lq[i] = 0.f; }

#pragma unroll
    for (int mt = 0; mt < 2; ++mt) {
        int grow0 = m0 + wr * 32 + mt * 16 + gid;
        int grow1 = grow0 + 8;
        bool v0 = grow0 < N, v1 = grow1 < N;
#pragma unroll
        for (int nt = 0; nt < 8; ++nt) {
            int gcol = wc * 64 + nt * 8 + tig * 2;
            float d0 = acc[mt][nt][0] + sbias[gcol];
            float d1 = acc[mt][nt][1] + sbias[gcol + 1];
            float d2 = acc[mt][nt][2] + sbias[gcol];
            float d3 = acc[mt][nt][3] + sbias[gcol + 1];
            if (v0) {
                *(float2*)(C + (size_t)grow0 * 128 + gcol) = make_float2(d0, d1);
                ls[nt * 2]     += d0; lq[nt * 2]     = fmaf(d0, d0, lq[nt * 2]);
                ls[nt * 2 + 1] += d1; lq[nt * 2 + 1] = fmaf(d1, d1, lq[nt * 2 + 1]);
            }
            if (v1) {
                *(float2*)(C + (size_t)grow1 * 128 + gcol) = make_float2(d2, d3);
                ls[nt * 2]     += d2; lq[nt * 2]     = fmaf(d2, d2, lq[nt * 2]);
                ls[nt * 2 + 1] += d3; lq[nt * 2 + 1] = fmaf(d3, d3, lq[nt * 2 + 1]);
            }
        }
    }
#pragma unroll
    for (int d = 4; d < 32; d <<= 1) {
#pragma unroll
        for (int i = 0; i < 16; ++i) {
            ls[i] += __shfl_xor_sync(0xFFFFFFFFu, ls[i], d);
            lq[i] += __shfl_xor_sync(0xFFFFFFFFu, lq[i], d);
        }
    }
    if (gid == 0) {
#pragma unroll
        for (int i = 0; i < 16; ++i) {
            int col = wc * 64 + (i >> 1) * 8 + tig * 2 + (i & 1);
            atomicAdd(&sS[col], ls[i]);
            atomicAdd(&sQ[col], lq[i]);
        }
    }
    __syncthreads();
    if (tid < 128) {
        atomicAdd(&statSum[tid], sS[tid]);
        atomicAdd(&statSq[tid],  sQ[tid]);
    }
}

// out = relu(BN2(out)), BN2 affine computed per block from g_stats.
__global__ void __launch_bounds__(256)
bnrelu_kernel(float* __restrict__ out,
              const float* __restrict__ gamma, const float* __restrict__ beta,
              int N, float invN) {
    __shared__ float s_a[128], s_c[128];
    int tid = threadIdx.x;
    if (tid < 128) {
        float mu  = g_stats[256 + tid] * invN;
        float var = g_stats[384 + tid] * invN - mu * mu;
        float a = gamma[tid] * rsqrtf(var + 1e-5f);
        s_a[tid] = a;
        s_c[tid] = beta[tid] - mu * a;
    }
    __syncthreads();
    int c4 = (tid & 31) << 2;
    float4 a4  = *(const float4*)(s_a + c4);
    float4 c4v = *(const float4*)(s_c + c4);
    int rows_per_iter = gridDim.x * (blockDim.x >> 5);
    int r = blockIdx.x * (blockDim.x >> 5) + (tid >> 5);
    float4* o4 = (float4*)out;
    for (; r < N; r += rows_per_iter) {
        size_t idx = (size_t)r * 32 + (tid & 31);
        float4 v = o4[idx];
        v.x = fmaxf(fmaf(v.x, a4.x, c4v.x), 0.f);
        v.y = fmaxf(fmaf(v.y, a4.y, c4v.y), 0.f);
        v.z = fmaxf(fmaf(v.z, a4.z, c4v.z), 0.f);
        v.w = fmaxf(fmaf(v.w, a4.w, c4v.w), 0.f);
        o4[idx] = v;
    }
}

// ---------------------------------------------------------------------------
extern "C" void kernel_launch(void* const* d_in, const int* in_sizes, int n_in,
                              void* d_out, int out_size) {
    const float* x   = (const float*)d_in[0];
    const void*  ei  = d_in[1];
    const float* eps = (const float*)d_in[2];
    const float* W1  = (const float*)d_in[3];
    const float* b1  = (const float*)d_in[4];
    const float* g1  = (const float*)d_in[5];
    const float* be1 = (const float*)d_in[6];
    const float* W2  = (const float*)d_in[7];
    const float* b2  = (const float*)d_in[8];
    const float* g2  = (const float*)d_in[9];
    const float* be2 = (const float*)d_in[10];

    int N = in_sizes[0] / 128;
    int E = in_sizes[1] / 2;
    if (E > MAXE) E = MAXE;
    float* out = (float*)d_out;
    float invN = 1.f / (float)N;
    int nb = (N + 1023) / 1024;

    cudaFuncSetAttribute(gemm_mma<false>,
                         cudaFuncAttributeMaxDynamicSharedMemorySize, SMEM_GEMM);
    cudaFuncSetAttribute(gemm_mma<true>,
                         cudaFuncAttributeMaxDynamicSharedMemorySize, SMEM_GEMM);

    init_kernel<<<(N + 256) / 256, 256>>>((const int*)ei, E, N);
    hist_kernel<<<(E + 1023) / 1024, 256>>>(ei, E);
    csr_scan<<<nb, 256>>>(N, nb);
    permute_kernel<<<(E + 1023) / 1024, 256>>>(ei, E);

    int ablocks = (N * 32 + 255) / 256;
    aggregate_kernel<<<ablocks, 256>>>(x, eps, N);

    int gblocks = (N + 127) / 128;
    gemm_mma<false><<<gblocks, 256, SMEM_GEMM>>>(W1, b1, nullptr, nullptr,
                                                 nullptr, N, invN);
    gemm_mma<true><<<gblocks, 256, SMEM_GEMM>>>(W2, b2, g1, be1,
                                                out, N, invN);
    bnrelu_kernel<<<592, 256>>>(out, g2, be2, N, invN);
}

// round 12
// speedup vs baseline: 1.0439x; 1.0439x over previous
#include <cuda_runtime.h>
#include <cuda_fp16.h>
#include <cstdint>

// ---------------------------------------------------------------------------
// GIN block. 8-kernel pipeline:
//   init (dtype detect + zero) -> hist (atomicAdd, stores per-edge rank) ->
//   single-pass lookback scan -> permute (ATOMIC-FREE: off[dst]+rank) ->
//   aggregate (CSR gather, full occupancy) ->
//   gemm1 (mma.sync 3xFP16-split m16n8k16, fused BN1 stats) ->
//   gemm2 (BN1+ReLU folded on load, fused BN2 stats) -> bnrelu.
// R8: don't fuse the gather into the 1-CTA/SM GEMM.
// R6: __device__ symbols only from device code.
// R11: per-thread ILP widening LOSES on these atomic kernels (fewer warps);
//      keep 2-edge/thread shapes, remove the atomic algebraically instead.
// ---------------------------------------------------------------------------

#define MAXN 50048
#define MAXE 1600000

__device__ __align__(16) float g_agg[MAXN * 128];
__device__ __align__(16) float g_h1[MAXN * 128];
__device__ float g_stats[512];   // [sum1, sumsq1, sum2, sumsq2] x 128
__device__ int   g_deg[MAXN + 1];
__device__ int   g_off[MAXN + 1];
__device__ unsigned long long g_look[64];  // lookback: flag(hi32) | value(lo32)
__device__ int   g_rank[MAXE];   // per-edge rank among same-dst edges
__device__ int   g_srcsorted[MAXE];
__device__ int   g_is64;

// ---------------------------------------------------------------------------
__global__ void init_kernel(const int* __restrict__ ei32, int E, int N) {
    int i = blockIdx.x * blockDim.x + threadIdx.x;
    if (i <= N) g_deg[i] = 0;
    if (i < 512) g_stats[i] = 0.f;
    if (i < 64) g_look[i] = 0ull;
    if (blockIdx.x == 0) {
        __shared__ int nz;
        if (threadIdx.x == 0) nz = 0;
        __syncthreads();
        int pairs = E < 2048 ? E : 2048;
        int cnt = 0;
        for (int j = threadIdx.x; j < pairs; j += blockDim.x)
            if (ei32[2 * j + 1] != 0) cnt++;
        if (cnt) atomicOr(&nz, 1);
        __syncthreads();
        if (threadIdx.x == 0) g_is64 = (nz == 0) ? 1 : 0;
    }
}

__device__ __forceinline__ int load_idx(const void* ei, long long i) {
    return g_is64 ? (int)((const long long*)ei)[i] : ((const int*)ei)[i];
}

// 2 edges per thread; atomicAdd return value IS this edge's rank -> store it.
__global__ void hist_kernel(const void* __restrict__ ei, int E) {
    int i = (blockIdx.x * blockDim.x + threadIdx.x) * 2;
    if (i < E) {
        int dst = load_idx(ei, (long long)E + i);
        g_rank[i] = atomicAdd(&g_deg[dst], 1);
    }
    if (i + 1 < E) {
        int dst = load_idx(ei, (long long)E + i + 1);
        g_rank[i + 1] = atomicAdd(&g_deg[dst], 1);
    }
}

// Single-pass exclusive scan of g_deg via decoupled lookback (nb <= 49).
__global__ void __launch_bounds__(256) csr_scan(int N, int nb) {
    __shared__ int sh[256];
    __shared__ int sbase;
    int b = blockIdx.x, tid = threadIdx.x;
    int i0 = b * 1024 + tid * 4;
    int d0 = 0, d1 = 0, d2 = 0, d3 = 0;
    if (i0 + 0 < N) d0 = g_deg[i0 + 0];
    if (i0 + 1 < N) d1 = g_deg[i0 + 1];
    if (i0 + 2 < N) d2 = g_deg[i0 + 2];
    if (i0 + 3 < N) d3 = g_deg[i0 + 3];
    int tsum = d0 + d1 + d2 + d3;
    sh[tid] = tsum;
    __syncthreads();
    for (int d = 1; d < 256; d <<= 1) {
        int t = (tid >= d) ? sh[tid - d] : 0;
        __syncthreads();
        sh[tid] += t;
        __syncthreads();
    }
    int agg = sh[255];
    if (tid == 0) {
        if (b == 0) {
            atomicExch(&g_look[0], (2ull << 32) | (unsigned)agg);
            sbase = 0;
        } else {
            atomicExch(&g_look[b], (1ull << 32) | (unsigned)agg);
            int ex = 0;
            int i = b - 1;
            while (true) {
                unsigned long long v;
                do { v = atomicAdd(&g_look[i], 0ull); } while ((v >> 32) == 0ull);
                ex += (int)(unsigned)v;
                if ((v >> 32) == 2ull) break;
                --i;
            }
            atomicExch(&g_look[b], (2ull << 32) | (unsigned)(ex + agg));
            sbase = ex;
        }
    }
    __syncthreads();
    int o0 = sbase + sh[tid] - tsum;
    int o1 = o0 + d0, o2 = o1 + d1, o3 = o2 + d2;
    if (i0 + 0 < N) g_off[i0 + 0] = o0;
    if (i0 + 1 < N) g_off[i0 + 1] = o1;
    if (i0 + 2 < N) g_off[i0 + 2] = o2;
    if (i0 + 3 < N) g_off[i0 + 3] = o3;
    if (b == nb - 1 && tid == 255) g_off[N] = sbase + agg;
}

// Atomic-free permute: position = off[dst] + rank[i]. 2 edges per thread.
__global__ void permute_kernel(const void* __restrict__ ei, int E) {
    int i = (blockIdx.x * blockDim.x + threadIdx.x) * 2;
    if (i < E) {
        int src = load_idx(ei, i);
        int dst = load_idx(ei, (long long)E + i);
        g_srcsorted[g_off[dst] + g_rank[i]] = src;
    }
    if (i + 1 < E) {
        int src = load_idx(ei, i + 1);
        int dst = load_idx(ei, (long long)E + i + 1);
        g_srcsorted[g_off[dst] + g_rank[i + 1]] = src;
    }
}

// One warp per node: acc = (1+eps)*x[node] + sum of neighbor rows; one store.
// (R10 4-wide form — the 8-wide R11 variant regressed.)
__global__ void aggregate_kernel(const float* __restrict__ x,
                                 const float* __restrict__ eps, int N) {
    int w = (int)((blockIdx.x * blockDim.x + threadIdx.x) >> 5);
    if (w >= N) return;
    int lane = threadIdx.x & 31;
    const float4* x4 = (const float4*)x;
    float s = 1.f + eps[0];
    float4 acc = x4[(size_t)w * 32 + lane];
    acc.x *= s; acc.y *= s; acc.z *= s; acc.w *= s;
    float4 acc2 = make_float4(0.f, 0.f, 0.f, 0.f);
    int j = g_off[w], end = g_off[w + 1];
    for (; j + 3 < end; j += 4) {
        int s0 = g_srcsorted[j + 0];
        int s1 = g_srcsorted[j + 1];
        int s2 = g_srcsorted[j + 2];
        int s3 = g_srcsorted[j + 3];
        float4 v0 = x4[(size_t)s0 * 32 + lane];
        float4 v1 = x4[(size_t)s1 * 32 + lane];
        float4 v2 = x4[(size_t)s2 * 32 + lane];
        float4 v3 = x4[(size_t)s3 * 32 + lane];
        acc.x  += v0.x + v1.x; acc.y  += v0.y + v1.y;
        acc.z  += v0.z + v1.z; acc.w  += v0.w + v1.w;
        acc2.x += v2.x + v3.x; acc2.y += v2.y + v3.y;
        acc2.z += v2.z + v3.z; acc2.w += v2.w + v3.w;
    }
    for (; j < end; j++) {
        float4 v0 = x4[(size_t)g_srcsorted[j] * 32 + lane];
        acc.x += v0.x; acc.y += v0.y; acc.z += v0.z; acc.w += v0.w;
    }
    acc.x += acc2.x; acc.y += acc2.y; acc.z += acc2.z; acc.w += acc2.w;
    ((float4*)g_agg)[(size_t)w * 32 + lane] = acc;
}

// ---------------------------------------------------------------------------
// 3xFP16-split tensor-core GEMM (m16n8k16): D = Ain @ W^T + bias.
// x = hi + lo (fp16 each); D = Ahi*Bhi + Ahi*Blo + Alo*Bhi in fp32.
// SMEM: Ahi/Alo/Bhi/Blo as fp16x2 words [128 rows][68-word stride].
// CTA: 128x128 tile, 8 warps = 4 row-groups(32) x 2 col-groups(64).
// BN1=false (gemm1): A=g_agg, C=g_h1, stats -> g_stats[0/128].
// BN1=true  (gemm2): A=relu(BN1(g_h1)), C=outp, stats -> g_stats[256/384].
// ---------------------------------------------------------------------------
#define ROWW 68                         // words per row (64 + 4 pad)
#define SMO_AH   0
#define SMO_AL   (128*ROWW*4)           // 34816
#define SMO_BH   (2*128*ROWW*4)         // 69632
#define SMO_BL   (3*128*ROWW*4)         // 104448
#define SMO_BIAS (4*128*ROWW*4)         // 139264
#define SMO_SA   (SMO_BIAS + 512)
#define SMO_SC   (SMO_SA + 512)
#define SMO_SS   (SMO_SC + 512)
#define SMO_SQ   (SMO_SS + 512)
#define SMEM_GEMM (SMO_SQ + 512)        // 141824 bytes

__device__ __forceinline__ void split_h2(float x, float y,
                                         uint32_t& hi, uint32_t& lo) {
    __half hx = __float2half_rn(x), hy = __float2half_rn(y);
    __half lx = __float2half_rn(x - __half2float(hx));
    __half ly = __float2half_rn(y - __half2float(hy));
    hi = (uint32_t)__half_as_ushort(hx) | ((uint32_t)__half_as_ushort(hy) << 16);
    lo = (uint32_t)__half_as_ushort(lx) | ((uint32_t)__half_as_ushort(ly) << 16);
}

__device__ __forceinline__ void mma_f16(float* d, const uint32_t* a,
                                        uint32_t b0, uint32_t b1) {
    asm volatile(
        "mma.sync.aligned.m16n8k16.row.col.f32.f16.f16.f32 "
        "{%0,%1,%2,%3}, {%4,%5,%6,%7}, {%8,%9}, {%0,%1,%2,%3};"
        : "+f"(d[0]), "+f"(d[1]), "+f"(d[2]), "+f"(d[3])
        : "r"(a[0]), "r"(a[1]), "r"(a[2]), "r"(a[3]), "r"(b0), "r"(b1));
}

template <bool BN1>
__global__ void __launch_bounds__(256, 1)
gemm_mma(const float* __restrict__ W, const float* __restrict__ bias,
         const float* __restrict__ gamma, const float* __restrict__ beta,
         float* __restrict__ outp, int N, float invN) {
    const float* A  = BN1 ? g_h1 : g_agg;
    float* C        = BN1 ? outp : g_h1;
    float* statSum  = BN1 ? (g_stats + 256) : g_stats;
    float* statSq   = BN1 ? (g_stats + 384) : (g_stats + 128);

    extern __shared__ __align__(16) char smem[];
    uint32_t* Ah = (uint32_t*)(smem + SMO_AH);
    uint32_t* Al = (uint32_t*)(smem + SMO_AL);
    uint32_t* Bh = (uint32_t*)(smem + SMO_BH);
    uint32_t* Bl = (uint32_t*)(smem + SMO_BL);
    float* sbias = (float*)(smem + SMO_BIAS);
    float* s_a   = (float*)(smem + SMO_SA);
    float* s_c   = (float*)(smem + SMO_SC);
    float* sS    = (float*)(smem + SMO_SS);
    float* sQ    = (float*)(smem + SMO_SQ);

    int tid = threadIdx.x, wid = tid >> 5, lane = tid & 31;
    int wr = wid >> 1;        // 0..3 : rows wr*32 .. +32
    int wc = wid & 1;         // 0..1 : cols wc*64 .. +64
    int gid = lane >> 2;      // 0..7
    int tig = lane & 3;       // 0..3
    int m0 = blockIdx.x * 128;

    if (tid < 128) {
        sbias[tid] = bias[tid];
        sS[tid] = 0.f;
        sQ[tid] = 0.f;
        if (BN1) {
            float mu  = g_stats[tid] * invN;
            float var = g_stats[128 + tid] * invN - mu * mu;
            float a = gamma[tid] * rsqrtf(var + 1e-5f);
            s_a[tid] = a;
            s_c[tid] = beta[tid] - mu * a;
        }
    }
    __syncthreads();

    // ---- load + split A tile ----
#pragma unroll
    for (int it = 0; it < 16; ++it) {
        int idx = tid + it * 256;        // 0..4095
        int row = idx >> 5;              // 0..127
        int kq  = idx & 31;              // float4 index 0..31
        int gm = m0 + row; if (gm >= N) gm = N - 1;
        float4 v = *(const float4*)(A + (size_t)gm * 128 + kq * 4);
        if (BN1) {
            int k0 = kq * 4;
            v.x = fmaxf(fmaf(v.x, s_a[k0 + 0], s_c[k0 + 0]), 0.f);
            v.y = fmaxf(fmaf(v.y, s_a[k0 + 1], s_c[k0 + 1]), 0.f);
            v.z = fmaxf(fmaf(v.z, s_a[k0 + 2], s_c[k0 + 2]), 0.f);
            v.w = fmaxf(fmaf(v.w, s_a[k0 + 3], s_c[k0 + 3]), 0.f);
        }
        uint32_t h0, l0, h1, l1;
        split_h2(v.x, v.y, h0, l0);
        split_h2(v.z, v.w, h1, l1);
        int o = row * ROWW + kq * 2;
        *(uint2*)(Ah + o) = make_uint2(h0, h1);
        *(uint2*)(Al + o) = make_uint2(l0, l1);
    }
    // ---- load + split W ----
#pragma unroll
    for (int it = 0; it < 16; ++it) {
        int idx = tid + it * 256;
        int row = idx >> 5;              // n
        int kq  = idx & 31;
        float4 v = *(const float4*)(W + (size_t)row * 128 + kq * 4);
        uint32_t h0, l0, h1, l1;
        split_h2(v.x, v.y, h0, l0);
        split_h2(v.z, v.w, h1, l1);
        int o = row * ROWW + kq * 2;
        *(uint2*)(Bh + o) = make_uint2(h0, h1);
        *(uint2*)(Bl + o) = make_uint2(l0, l1);
    }
    __syncthreads();

    // ---- mainloop: 8 K-chunks of 16 ----
    float acc[2][8][4];
#pragma unroll
    for (int mt = 0; mt < 2; ++mt)
#pragma unroll
        for (int nt = 0; nt < 8; ++nt)
#pragma unroll
            for (int r = 0; r < 4; ++r) acc[mt][nt][r] = 0.f;

#pragma unroll
    for (int ks = 0; ks < 8; ++ks) {
        int kw0 = ks * 8;  // word offset of this K-chunk
        uint32_t ahi[2][4], alo[2][4];
#pragma unroll
        for (int mt = 0; mt < 2; ++mt) {
            int r0 = wr * 32 + mt * 16 + gid;
            ahi[mt][0] = Ah[r0 * ROWW + kw0 + tig];
            ahi[mt][1] = Ah[(r0 + 8) * ROWW + kw0 + tig];
            ahi[mt][2] = Ah[r0 * ROWW + kw0 + tig + 4];
            ahi[mt][3] = Ah[(r0 + 8) * ROWW + kw0 + tig + 4];
            alo[mt][0] = Al[r0 * ROWW + kw0 + tig];
            alo[mt][1] = Al[(r0 + 8) * ROWW + kw0 + tig];
            alo[mt][2] = Al[r0 * ROWW + kw0 + tig + 4];
            alo[mt][3] = Al[(r0 + 8) * ROWW + kw0 + tig + 4];
        }
#pragma unroll
        for (int nt = 0; nt < 8; ++nt) {
            int n = wc * 64 + nt * 8 + gid;
            uint32_t bh0 = Bh[n * ROWW + kw0 + tig];
            uint32_t bh1 = Bh[n * ROWW + kw0 + tig + 4];
            uint32_t bl0 = Bl[n * ROWW + kw0 + tig];
            uint32_t bl1 = Bl[n * ROWW + kw0 + tig + 4];
#pragma unroll
            for (int mt = 0; mt < 2; ++mt) {
                mma_f16(acc[mt][nt], ahi[mt], bh0, bh1);
                mma_f16(acc[mt][nt], ahi[mt], bl0, bl1);
                mma_f16(acc[mt][nt], alo[mt], bh0, bh1);
            }
        }
    }

    // ---- epilogue: bias add, store, fused column stats ----
    float ls[16], lq[16];
#pragma unroll
    for (int i = 0; i < 16; ++i) { ls[i] = 0.f; lq[i] = 0.f; }

#pragma unroll
    for (int mt = 0; mt < 2; ++mt) {
        int grow0 = m0 + wr * 32 + mt * 16 + gid;
        int grow1 = grow0 + 8;
        bool v0 = grow0 < N, v1 = grow1 < N;
#pragma unroll
        for (int nt = 0; nt < 8; ++nt) {
            int gcol = wc * 64 + nt * 8 + tig * 2;
            float d0 = acc[mt][nt][0] + sbias[gcol];
            float d1 = acc[mt][nt][1] + sbias[gcol + 1];
            float d2 = acc[mt][nt][2] + sbias[gcol];
            float d3 = acc[mt][nt][3] + sbias[gcol + 1];
            if (v0) {
                *(float2*)(C + (size_t)grow0 * 128 + gcol) = make_float2(d0, d1);
                ls[nt * 2]     += d0; lq[nt * 2]     = fmaf(d0, d0, lq[nt * 2]);
                ls[nt * 2 + 1] += d1; lq[nt * 2 + 1] = fmaf(d1, d1, lq[nt * 2 + 1]);
            }
            if (v1) {
                *(float2*)(C + (size_t)grow1 * 128 + gcol) = make_float2(d2, d3);
                ls[nt * 2]     += d2; lq[nt * 2]     = fmaf(d2, d2, lq[nt * 2]);
                ls[nt * 2 + 1] += d3; lq[nt * 2 + 1] = fmaf(d3, d3, lq[nt * 2 + 1]);
            }
        }
    }
#pragma unroll
    for (int d = 4; d < 32; d <<= 1) {
#pragma unroll
        for (int i = 0; i < 16; ++i) {
            ls[i] += __shfl_xor_sync(0xFFFFFFFFu, ls[i], d);
            lq[i] += __shfl_xor_sync(0xFFFFFFFFu, lq[i], d);
        }
    }
    if (gid == 0) {
#pragma unroll
        for (int i = 0; i < 16; ++i) {
            int col = wc * 64 + (i >> 1) * 8 + tig * 2 + (i & 1);
            atomicAdd(&sS[col], ls[i]);
            atomicAdd(&sQ[col], lq[i]);
        }
    }
    __syncthreads();
    if (tid < 128) {
        atomicAdd(&statSum[tid], sS[tid]);
        atomicAdd(&statSq[tid],  sQ[tid]);
    }
}

// out = relu(BN2(out)), BN2 affine computed per block from g_stats.
__global__ void __launch_bounds__(256)
bnrelu_kernel(float* __restrict__ out,
              const float* __restrict__ gamma, const float* __restrict__ beta,
              int N, float invN) {
    __shared__ float s_a[128], s_c[128];
    int tid = threadIdx.x;
    if (tid < 128) {
        float mu  = g_stats[256 + tid] * invN;
        float var = g_stats[384 + tid] * invN - mu * mu;
        float a = gamma[tid] * rsqrtf(var + 1e-5f);
        s_a[tid] = a;
        s_c[tid] = beta[tid] - mu * a;
    }
    __syncthreads();
    int c4 = (tid & 31) << 2;
    float4 a4  = *(const float4*)(s_a + c4);
    float4 c4v = *(const float4*)(s_c + c4);
    int rows_per_iter = gridDim.x * (blockDim.x >> 5);
    int r = blockIdx.x * (blockDim.x >> 5) + (tid >> 5);
    float4* o4 = (float4*)out;
    for (; r < N; r += rows_per_iter) {
        size_t idx = (size_t)r * 32 + (tid & 31);
        float4 v = o4[idx];
        v.x = fmaxf(fmaf(v.x, a4.x, c4v.x), 0.f);
        v.y = fmaxf(fmaf(v.y, a4.y, c4v.y), 0.f);
        v.z = fmaxf(fmaf(v.z, a4.z, c4v.z), 0.f);
        v.w = fmaxf(fmaf(v.w, a4.w, c4v.w), 0.f);
        o4[idx] = v;
    }
}

// ---------------------------------------------------------------------------
extern "C" void kernel_launch(void* const* d_in, const int* in_sizes, int n_in,
                              void* d_out, int out_size) {
    const float* x   = (const float*)d_in[0];
    const void*  ei  = d_in[1];
    const float* eps = (const float*)d_in[2];
    const float* W1  = (const float*)d_in[3];
    const float* b1  = (const float*)d_in[4];
    const float* g1  = (const float*)d_in[5];
    const float* be1 = (const float*)d_in[6];
    const float* W2  = (const float*)d_in[7];
    const float* b2  = (const float*)d_in[8];
    const float* g2  = (const float*)d_in[9];
    const float* be2 = (const float*)d_in[10];

    int N = in_sizes[0] / 128;
    int E = in_sizes[1] / 2;
    if (E > MAXE) E = MAXE;
    float* out = (float*)d_out;
    float invN = 1.f / (float)N;
    int nb = (N + 1023) / 1024;

    cudaFuncSetAttribute(gemm_mma<false>,
                         cudaFuncAttributeMaxDynamicSharedMemorySize, SMEM_GEMM);
    cudaFuncSetAttribute(gemm_mma<true>,
                         cudaFuncAttributeMaxDynamicSharedMemorySize, SMEM_GEMM);

    init_kernel<<<(N + 256) / 256, 256>>>((const int*)ei, E, N);
    hist_kernel<<<(E + 511) / 512, 256>>>(ei, E);
    csr_scan<<<nb, 256>>>(N, nb);
    permute_kernel<<<(E + 511) / 512, 256>>>(ei, E);

    int ablocks = (N * 32 + 255) / 256;
    aggregate_kernel<<<ablocks, 256>>>(x, eps, N);

    int gblocks = (N + 127) / 128;
    gemm_mma<false><<<gblocks, 256, SMEM_GEMM>>>(W1, b1, nullptr, nullptr,
                                                 nullptr, N, invN);
    gemm_mma<true><<<gblocks, 256, SMEM_GEMM>>>(W2, b2, g1, be1,
                                                out, N, invN);
    bnrelu_kernel<<<592, 256>>>(out, g2, be2, N, invN);
}

// round 13
// speedup vs baseline: 1.0816x; 1.0361x over previous
#include <cuda_runtime.h>
#include <cuda_fp16.h>
#include <cstdint>

// ---------------------------------------------------------------------------
// GIN block. 6-kernel pipeline (scan & permute ELIMINATED via bucket CSR):
//   init (dtype detect + zero) ->
//   bucket (atomicAdd rank -> g_bucket[dst*64+rank]=src, overflow list) ->
//   aggregate (per-node bucket gather, full occupancy) ->
//   gemm1 (mma.sync 3xFP16-split m16n8k16, fused BN1 stats) ->
//   gemm2 (BN1+ReLU folded on load, fused BN2 stats) -> bnrelu.
// R8:  don't fuse the gather into the 1-CTA/SM GEMM.
// R6:  __device__ symbols only from device code.
// R11: per-thread ILP widening loses on atomic kernels (fewer warps).
// R12: algebraic atomic elimination wins; extend: fixed-slot buckets kill
//      the scan AND the permute pass outright.
// ---------------------------------------------------------------------------

#define MAXN 50048
#define MAXE 1600000
#define BK   64         // bucket slots per node (Poisson(16) max deg ~40)

__device__ __align__(16) float g_agg[MAXN * 128];
__device__ __align__(16) float g_h1[MAXN * 128];
__device__ float g_stats[512];   // [sum1, sumsq1, sum2, sumsq2] x 128
__device__ int   g_deg[MAXN];
__device__ int   g_bucket[MAXN * BK];
__device__ int   g_ovf[2 * MAXE];  // (dst, src) pairs for rank >= BK
__device__ int   g_ovfcnt;
__device__ int   g_is64;

// ---------------------------------------------------------------------------
__global__ void init_kernel(const int* __restrict__ ei32, int E, int N) {
    int i = blockIdx.x * blockDim.x + threadIdx.x;
    if (i < N) g_deg[i] = 0;
    if (i < 512) g_stats[i] = 0.f;
    if (i == 0) g_ovfcnt = 0;
    if (blockIdx.x == 0) {
        __shared__ int nz;
        if (threadIdx.x == 0) nz = 0;
        __syncthreads();
        int pairs = E < 2048 ? E : 2048;
        int cnt = 0;
        for (int j = threadIdx.x; j < pairs; j += blockDim.x)
            if (ei32[2 * j + 1] != 0) cnt++;
        if (cnt) atomicOr(&nz, 1);
        __syncthreads();
        if (threadIdx.x == 0) g_is64 = (nz == 0) ? 1 : 0;
    }
}

__device__ __forceinline__ int load_idx(const void* ei, long long i) {
    return g_is64 ? (int)((const long long*)ei)[i] : ((const int*)ei)[i];
}

// Histogram + direct bucket write. 2 edges per thread (R11 lesson: keep warps).
__global__ void bucket_kernel(const void* __restrict__ ei, int E) {
    int i = (blockIdx.x * blockDim.x + threadIdx.x) * 2;
#pragma unroll
    for (int t = 0; t < 2; ++t, ++i) {
        if (i >= E) return;
        int src = load_idx(ei, i);
        int dst = load_idx(ei, (long long)E + i);
        int r = atomicAdd(&g_deg[dst], 1);
        if (r < BK) {
            g_bucket[dst * BK + r] = src;
        } else {
            int o = atomicAdd(&g_ovfcnt, 1);
            g_ovf[2 * o] = dst;
            g_ovf[2 * o + 1] = src;
        }
    }
}

// One warp per node: acc = (1+eps)*x[node] + sum of bucketed neighbor rows.
// Owning warp also drains any overflow entries targeting it (expected: none).
__global__ void aggregate_kernel(const float* __restrict__ x,
                                 const float* __restrict__ eps, int N) {
    int w = (int)((blockIdx.x * blockDim.x + threadIdx.x) >> 5);
    if (w >= N) return;
    int lane = threadIdx.x & 31;
    const float4* x4 = (const float4*)x;
    float s = 1.f + eps[0];
    float4 acc = x4[(size_t)w * 32 + lane];
    acc.x *= s; acc.y *= s; acc.z *= s; acc.w *= s;
    float4 acc2 = make_float4(0.f, 0.f, 0.f, 0.f);
    int deg = g_deg[w];
    int cnt = deg < BK ? deg : BK;
    const int* bk = g_bucket + (size_t)w * BK;
    int j = 0;
    for (; j + 3 < cnt; j += 4) {
        int s0 = bk[j + 0];
        int s1 = bk[j + 1];
        int s2 = bk[j + 2];
        int s3 = bk[j + 3];
        float4 v0 = x4[(size_t)s0 * 32 + lane];
        float4 v1 = x4[(size_t)s1 * 32 + lane];
        float4 v2 = x4[(size_t)s2 * 32 + lane];
        float4 v3 = x4[(size_t)s3 * 32 + lane];
        acc.x  += v0.x + v1.x; acc.y  += v0.y + v1.y;
        acc.z  += v0.z + v1.z; acc.w  += v0.w + v1.w;
        acc2.x += v2.x + v3.x; acc2.y += v2.y + v3.y;
        acc2.z += v2.z + v3.z; acc2.w += v2.w + v3.w;
    }
    for (; j < cnt; j++) {
        float4 v0 = x4[(size_t)bk[j] * 32 + lane];
        acc.x += v0.x; acc.y += v0.y; acc.z += v0.z; acc.w += v0.w;
    }
    if (deg > BK) {  // drain overflow entries for this node (rare/none)
        int oc = g_ovfcnt;
        for (int i = 0; i < oc; ++i) {
            if (g_ovf[2 * i] == w) {
                float4 v0 = x4[(size_t)g_ovf[2 * i + 1] * 32 + lane];
                acc.x += v0.x; acc.y += v0.y; acc.z += v0.z; acc.w += v0.w;
            }
        }
    }
    acc.x += acc2.x; acc.y += acc2.y; acc.z += acc2.z; acc.w += acc2.w;
    ((float4*)g_agg)[(size_t)w * 32 + lane] = acc;
}

// ---------------------------------------------------------------------------
// 3xFP16-split tensor-core GEMM (m16n8k16): D = Ain @ W^T + bias.
// x = hi + lo (fp16 each); D = Ahi*Bhi + Ahi*Blo + Alo*Bhi in fp32.
// SMEM: Ahi/Alo/Bhi/Blo as fp16x2 words [128 rows][68-word stride].
// CTA: 128x128 tile, 8 warps = 4 row-groups(32) x 2 col-groups(64).
// BN1=false (gemm1): A=g_agg, C=g_h1, stats -> g_stats[0/128].
// BN1=true  (gemm2): A=relu(BN1(g_h1)), C=outp, stats -> g_stats[256/384].
// ---------------------------------------------------------------------------
#define ROWW 68                         // words per row (64 + 4 pad)
#define SMO_AH   0
#define SMO_AL   (128*ROWW*4)           // 34816
#define SMO_BH   (2*128*ROWW*4)         // 69632
#define SMO_BL   (3*128*ROWW*4)         // 104448
#define SMO_BIAS (4*128*ROWW*4)         // 139264
#define SMO_SA   (SMO_BIAS + 512)
#define SMO_SC   (SMO_SA + 512)
#define SMO_SS   (SMO_SC + 512)
#define SMO_SQ   (SMO_SS + 512)
#define SMEM_GEMM (SMO_SQ + 512)        // 141824 bytes

__device__ __forceinline__ void split_h2(float x, float y,
                                         uint32_t& hi, uint32_t& lo) {
    __half hx = __float2half_rn(x), hy = __float2half_rn(y);
    __half lx = __float2half_rn(x - __half2float(hx));
    __half ly = __float2half_rn(y - __half2float(hy));
    hi = (uint32_t)__half_as_ushort(hx) | ((uint32_t)__half_as_ushort(hy) << 16);
    lo = (uint32_t)__half_as_ushort(lx) | ((uint32_t)__half_as_ushort(ly) << 16);
}

__device__ __forceinline__ void mma_f16(float* d, const uint32_t* a,
                                        uint32_t b0, uint32_t b1) {
    asm volatile(
        "mma.sync.aligned.m16n8k16.row.col.f32.f16.f16.f32 "
        "{%0,%1,%2,%3}, {%4,%5,%6,%7}, {%8,%9}, {%0,%1,%2,%3};"
        : "+f"(d[0]), "+f"(d[1]), "+f"(d[2]), "+f"(d[3])
        : "r"(a[0]), "r"(a[1]), "r"(a[2]), "r"(a[3]), "r"(b0), "r"(b1));
}

template <bool BN1>
__global__ void __launch_bounds__(256, 1)
gemm_mma(const float* __restrict__ W, const float* __restrict__ bias,
         const float* __restrict__ gamma, const float* __restrict__ beta,
         float* __restrict__ outp, int N, float invN) {
    const float* A  = BN1 ? g_h1 : g_agg;
    float* C        = BN1 ? outp : g_h1;
    float* statSum  = BN1 ? (g_stats + 256) : g_stats;
    float* statSq   = BN1 ? (g_stats + 384) : (g_stats + 128);

    extern __shared__ __align__(16) char smem[];
    uint32_t* Ah = (uint32_t*)(smem + SMO_AH);
    uint32_t* Al = (uint32_t*)(smem + SMO_AL);
    uint32_t* Bh = (uint32_t*)(smem + SMO_BH);
    uint32_t* Bl = (uint32_t*)(smem + SMO_BL);
    float* sbias = (float*)(smem + SMO_BIAS);
    float* s_a   = (float*)(smem + SMO_SA);
    float* s_c   = (float*)(smem + SMO_SC);
    float* sS    = (float*)(smem + SMO_SS);
    float* sQ    = (float*)(smem + SMO_SQ);

    int tid = threadIdx.x, wid = tid >> 5, lane = tid & 31;
    int wr = wid >> 1;        // 0..3 : rows wr*32 .. +32
    int wc = wid & 1;         // 0..1 : cols wc*64 .. +64
    int gid = lane >> 2;      // 0..7
    int tig = lane & 3;       // 0..3
    int m0 = blockIdx.x * 128;

    if (tid < 128) {
        sbias[tid] = bias[tid];
        sS[tid] = 0.f;
        sQ[tid] = 0.f;
        if (BN1) {
            float mu  = g_stats[tid] * invN;
            float var = g_stats[128 + tid] * invN - mu * mu;
            float a = gamma[tid] * rsqrtf(var + 1e-5f);
            s_a[tid] = a;
            s_c[tid] = beta[tid] - mu * a;
        }
    }
    __syncthreads();

    // ---- load + split A tile ----
#pragma unroll
    for (int it = 0; it < 16; ++it) {
        int idx = tid + it * 256;        // 0..4095
        int row = idx >> 5;              // 0..127
        int kq  = idx & 31;              // float4 index 0..31
        int gm = m0 + row; if (gm >= N) gm = N - 1;
        float4 v = *(const float4*)(A + (size_t)gm * 128 + kq * 4);
        if (BN1) {
            int k0 = kq * 4;
            v.x = fmaxf(fmaf(v.x, s_a[k0 + 0], s_c[k0 + 0]), 0.f);
            v.y = fmaxf(fmaf(v.y, s_a[k0 + 1], s_c[k0 + 1]), 0.f);
            v.z = fmaxf(fmaf(v.z, s_a[k0 + 2], s_c[k0 + 2]), 0.f);
            v.w = fmaxf(fmaf(v.w, s_a[k0 + 3], s_c[k0 + 3]), 0.f);
        }
        uint32_t h0, l0, h1, l1;
        split_h2(v.x, v.y, h0, l0);
        split_h2(v.z, v.w, h1, l1);
        int o = row * ROWW + kq * 2;
        *(uint2*)(Ah + o) = make_uint2(h0, h1);
        *(uint2*)(Al + o) = make_uint2(l0, l1);
    }
    // ---- load + split W ----
#pragma unroll
    for (int it = 0; it < 16; ++it) {
        int idx = tid + it * 256;
        int row = idx >> 5;              // n
        int kq  = idx & 31;
        float4 v = *(const float4*)(W + (size_t)row * 128 + kq * 4);
        uint32_t h0, l0, h1, l1;
        split_h2(v.x, v.y, h0, l0);
        split_h2(v.z, v.w, h1, l1);
        int o = row * ROWW + kq * 2;
        *(uint2*)(Bh + o) = make_uint2(h0, h1);
        *(uint2*)(Bl + o) = make_uint2(l0, l1);
    }
    __syncthreads();

    // ---- mainloop: 8 K-chunks of 16 ----
    float acc[2][8][4];
#pragma unroll
    for (int mt = 0; mt < 2; ++mt)
#pragma unroll
        for (int nt = 0; nt < 8; ++nt)
#pragma unroll
            for (int r = 0; r < 4; ++r) acc[mt][nt][r] = 0.f;

#pragma unroll
    for (int ks = 0; ks < 8; ++ks) {
        int kw0 = ks * 8;  // word offset of this K-chunk
        uint32_t ahi[2][4], alo[2][4];
#pragma unroll
        for (int mt = 0; mt < 2; ++mt) {
            int r0 = wr * 32 + mt * 16 + gid;
            ahi[mt][0] = Ah[r0 * ROWW + kw0 + tig];
            ahi[mt][1] = Ah[(r0 + 8) * ROWW + kw0 + tig];
            ahi[mt][2] = Ah[r0 * ROWW + kw0 + tig + 4];
            ahi[mt][3] = Ah[(r0 + 8) * ROWW + kw0 + tig + 4];
            alo[mt][0] = Al[r0 * ROWW + kw0 + tig];
            alo[mt][1] = Al[(r0 + 8) * ROWW + kw0 + tig];
            alo[mt][2] = Al[r0 * ROWW + kw0 + tig + 4];
            alo[mt][3] = Al[(r0 + 8) * ROWW + kw0 + tig + 4];
        }
#pragma unroll
        for (int nt = 0; nt < 8; ++nt) {
            int n = wc * 64 + nt * 8 + gid;
            uint32_t bh0 = Bh[n * ROWW + kw0 + tig];
            uint32_t bh1 = Bh[n * ROWW + kw0 + tig + 4];
            uint32_t bl0 = Bl[n * ROWW + kw0 + tig];
            uint32_t bl1 = Bl[n * ROWW + kw0 + tig + 4];
#pragma unroll
            for (int mt = 0; mt < 2; ++mt) {
                mma_f16(acc[mt][nt], ahi[mt], bh0, bh1);
                mma_f16(acc[mt][nt], ahi[mt], bl0, bl1);
                mma_f16(acc[mt][nt], alo[mt], bh0, bh1);
            }
        }
    }

    // ---- epilogue: bias add, store, fused column stats ----
    float ls[16], lq[16];
#pragma unroll
    for (int i = 0; i < 16; ++i) { ls[i] = 0.f; lq[i] = 0.f; }

#pragma unroll
    for (int mt = 0; mt < 2; ++mt) {
        int grow0 = m0 + wr * 32 + mt * 16 + gid;
        int grow1 = grow0 + 8;
        bool v0 = grow0 < N, v1 = grow1 < N;
#pragma unroll
        for (int nt = 0; nt < 8; ++nt) {
            int gcol = wc * 64 + nt * 8 + tig * 2;
            float d0 = acc[mt][nt][0] + sbias[gcol];
            float d1 = acc[mt][nt][1] + sbias[gcol + 1];
            float d2 = acc[mt][nt][2] + sbias[gcol];
            float d3 = acc[mt][nt][3] + sbias[gcol + 1];
            if (v0) {
                *(float2*)(C + (size_t)grow0 * 128 + gcol) = make_float2(d0, d1);
                ls[nt * 2]     += d0; lq[nt * 2]     = fmaf(d0, d0, lq[nt * 2]);
                ls[nt * 2 + 1] += d1; lq[nt * 2 + 1] = fmaf(d1, d1, lq[nt * 2 + 1]);
            }
            if (v1) {
                *(float2*)(C + (size_t)grow1 * 128 + gcol) = make_float2(d2, d3);
                ls[nt * 2]     += d2; lq[nt * 2]     = fmaf(d2, d2, lq[nt * 2]);
                ls[nt * 2 + 1] += d3; lq[nt * 2 + 1] = fmaf(d3, d3, lq[nt * 2 + 1]);
            }
        }
    }
#pragma unroll
    for (int d = 4; d < 32; d <<= 1) {
#pragma unroll
        for (int i = 0; i < 16; ++i) {
            ls[i] += __shfl_xor_sync(0xFFFFFFFFu, ls[i], d);
            lq[i] += __shfl_xor_sync(0xFFFFFFFFu, lq[i], d);
        }
    }
    if (gid == 0) {
#pragma unroll
        for (int i = 0; i < 16; ++i) {
            int col = wc * 64 + (i >> 1) * 8 + tig * 2 + (i & 1);
            atomicAdd(&sS[col], ls[i]);
            atomicAdd(&sQ[col], lq[i]);
        }
    }
    __syncthreads();
    if (tid < 128) {
        atomicAdd(&statSum[tid], sS[tid]);
        atomicAdd(&statSq[tid],  sQ[tid]);
    }
}

// out = relu(BN2(out)), BN2 affine computed per block from g_stats.
__global__ void __launch_bounds__(256)
bnrelu_kernel(float* __restrict__ out,
              const float* __restrict__ gamma, const float* __restrict__ beta,
              int N, float invN) {
    __shared__ float s_a[128], s_c[128];
    int tid = threadIdx.x;
    if (tid < 128) {
        float mu  = g_stats[256 + tid] * invN;
        float var = g_stats[384 + tid] * invN - mu * mu;
        float a = gamma[tid] * rsqrtf(var + 1e-5f);
        s_a[tid] = a;
        s_c[tid] = beta[tid] - mu * a;
    }
    __syncthreads();
    int c4 = (tid & 31) << 2;
    float4 a4  = *(const float4*)(s_a + c4);
    float4 c4v = *(const float4*)(s_c + c4);
    int rows_per_iter = gridDim.x * (blockDim.x >> 5);
    int r = blockIdx.x * (blockDim.x >> 5) + (tid >> 5);
    float4* o4 = (float4*)out;
    for (; r < N; r += rows_per_iter) {
        size_t idx = (size_t)r * 32 + (tid & 31);
        float4 v = o4[idx];
        v.x = fmaxf(fmaf(v.x, a4.x, c4v.x), 0.f);
        v.y = fmaxf(fmaf(v.y, a4.y, c4v.y), 0.f);
        v.z = fmaxf(fmaf(v.z, a4.z, c4v.z), 0.f);
        v.w = fmaxf(fmaf(v.w, a4.w, c4v.w), 0.f);
        o4[idx] = v;
    }
}

// ---------------------------------------------------------------------------
extern "C" void kernel_launch(void* const* d_in, const int* in_sizes, int n_in,
                              void* d_out, int out_size) {
    const float* x   = (const float*)d_in[0];
    const void*  ei  = d_in[1];
    const float* eps = (const float*)d_in[2];
    const float* W1  = (const float*)d_in[3];
    const float* b1  = (const float*)d_in[4];
    const float* g1  = (const float*)d_in[5];
    const float* be1 = (const float*)d_in[6];
    const float* W2  = (const float*)d_in[7];
    const float* b2  = (const float*)d_in[8];
    const float* g2  = (const float*)d_in[9];
    const float* be2 = (const float*)d_in[10];

    int N = in_sizes[0] / 128;
    int E = in_sizes[1] / 2;
    if (E > MAXE) E = MAXE;
    float* out = (float*)d_out;
    float invN = 1.f / (float)N;

    cudaFuncSetAttribute(gemm_mma<false>,
                         cudaFuncAttributeMaxDynamicSharedMemorySize, SMEM_GEMM);
    cudaFuncSetAttribute(gemm_mma<true>,
                         cudaFuncAttributeMaxDynamicSharedMemorySize, SMEM_GEMM);

    init_kernel<<<(N + 255) / 256, 256>>>((const int*)ei, E, N);
    bucket_kernel<<<(E + 511) / 512, 256>>>(ei, E);

    int ablocks = (N * 32 + 255) / 256;
    aggregate_kernel<<<ablocks, 256>>>(x, eps, N);

    int gblocks = (N + 127) / 128;
    gemm_mma<false><<<gblocks, 256, SMEM_GEMM>>>(W1, b1, nullptr, nullptr,
                                                 nullptr, N, invN);
    gemm_mma<true><<<gblocks, 256, SMEM_GEMM>>>(W2, b2, g1, be1,
                                                out, N, invN);
    bnrelu_kernel<<<592, 256>>>(out, g2, be2, N, invN);
}

// round 14
// speedup vs baseline: 1.1173x; 1.0330x over previous
#include <cuda_runtime.h>
#include <cuda_fp16.h>
#include <cstdint>

// ---------------------------------------------------------------------------
// GIN block. 6-kernel pipeline (bucket CSR, no scan/permute):
//   init -> bucket -> aggregate -> gemm1 -> gemm2 -> bnrelu.
// R13 ncu: 128x128 GEMM tile => 1 CTA/SM, regs=255 (spills), HBM 753 GB/s,
// tensor 23%. Fix: 64x128 tile, 2 CTAs/SM, warp tile 32x32, regs<=128.
// R8: don't fuse gather into GEMM. R6: device symbols only from device code.
// R11: keep warps on atomic kernels. R12/13: bucket CSR.
// ---------------------------------------------------------------------------

#define MAXN 50048
#define MAXE 1600000
#define BK   64         // bucket slots per node (Poisson(16) max deg ~40)

__device__ __align__(16) float g_agg[MAXN * 128];
__device__ __align__(16) float g_h1[MAXN * 128];
__device__ float g_stats[512];   // [sum1, sumsq1, sum2, sumsq2] x 128
__device__ int   g_deg[MAXN];
__device__ int   g_bucket[MAXN * BK];
__device__ int   g_ovf[2 * MAXE];  // (dst, src) pairs for rank >= BK
__device__ int   g_ovfcnt;
__device__ int   g_is64;

// ---------------------------------------------------------------------------
__global__ void init_kernel(const int* __restrict__ ei32, int E, int N) {
    int i = blockIdx.x * blockDim.x + threadIdx.x;
    if (i < N) g_deg[i] = 0;
    if (i < 512) g_stats[i] = 0.f;
    if (i == 0) g_ovfcnt = 0;
    if (blockIdx.x == 0) {
        __shared__ int nz;
        if (threadIdx.x == 0) nz = 0;
        __syncthreads();
        int pairs = E < 2048 ? E : 2048;
        int cnt = 0;
        for (int j = threadIdx.x; j < pairs; j += blockDim.x)
            if (ei32[2 * j + 1] != 0) cnt++;
        if (cnt) atomicOr(&nz, 1);
        __syncthreads();
        if (threadIdx.x == 0) g_is64 = (nz == 0) ? 1 : 0;
    }
}

__device__ __forceinline__ int load_idx(const void* ei, long long i) {
    return g_is64 ? (int)((const long long*)ei)[i] : ((const int*)ei)[i];
}

// Histogram + direct bucket write. 2 edges per thread.
__global__ void bucket_kernel(const void* __restrict__ ei, int E) {
    int i = (blockIdx.x * blockDim.x + threadIdx.x) * 2;
#pragma unroll
    for (int t = 0; t < 2; ++t, ++i) {
        if (i >= E) return;
        int src = load_idx(ei, i);
        int dst = load_idx(ei, (long long)E + i);
        int r = atomicAdd(&g_deg[dst], 1);
        if (r < BK) {
            g_bucket[dst * BK + r] = src;
        } else {
            int o = atomicAdd(&g_ovfcnt, 1);
            g_ovf[2 * o] = dst;
            g_ovf[2 * o + 1] = src;
        }
    }
}

// One warp per node: acc = (1+eps)*x[node] + sum of bucketed neighbor rows.
__global__ void aggregate_kernel(const float* __restrict__ x,
                                 const float* __restrict__ eps, int N) {
    int w = (int)((blockIdx.x * blockDim.x + threadIdx.x) >> 5);
    if (w >= N) return;
    int lane = threadIdx.x & 31;
    const float4* x4 = (const float4*)x;
    float s = 1.f + eps[0];
    float4 acc = x4[(size_t)w * 32 + lane];
    acc.x *= s; acc.y *= s; acc.z *= s; acc.w *= s;
    float4 acc2 = make_float4(0.f, 0.f, 0.f, 0.f);
    int deg = g_deg[w];
    int cnt = deg < BK ? deg : BK;
    const int* bk = g_bucket + (size_t)w * BK;
    int j = 0;
    for (; j + 3 < cnt; j += 4) {
        int s0 = bk[j + 0];
        int s1 = bk[j + 1];
        int s2 = bk[j + 2];
        int s3 = bk[j + 3];
        float4 v0 = x4[(size_t)s0 * 32 + lane];
        float4 v1 = x4[(size_t)s1 * 32 + lane];
        float4 v2 = x4[(size_t)s2 * 32 + lane];
        float4 v3 = x4[(size_t)s3 * 32 + lane];
        acc.x  += v0.x + v1.x; acc.y  += v0.y + v1.y;
        acc.z  += v0.z + v1.z; acc.w  += v0.w + v1.w;
        acc2.x += v2.x + v3.x; acc2.y += v2.y + v3.y;
        acc2.z += v2.z + v3.z; acc2.w += v2.w + v3.w;
    }
    for (; j < cnt; j++) {
        float4 v0 = x4[(size_t)bk[j] * 32 + lane];
        acc.x += v0.x; acc.y += v0.y; acc.z += v0.z; acc.w += v0.w;
    }
    if (deg > BK) {  // drain overflow entries for this node (rare/none)
        int oc = g_ovfcnt;
        for (int i = 0; i < oc; ++i) {
            if (g_ovf[2 * i] == w) {
                float4 v0 = x4[(size_t)g_ovf[2 * i + 1] * 32 + lane];
                acc.x += v0.x; acc.y += v0.y; acc.z += v0.z; acc.w += v0.w;
            }
        }
    }
    acc.x += acc2.x; acc.y += acc2.y; acc.z += acc2.z; acc.w += acc2.w;
    ((float4*)g_agg)[(size_t)w * 32 + lane] = acc;
}

// ---------------------------------------------------------------------------
// 3xFP16-split tensor-core GEMM (m16n8k16): D = Ain @ W^T + bias.
// CTA tile 64x128, 2 CTAs/SM. 8 warps = 2 row-groups(32) x 4 col-groups(32).
// SMEM: A(hi/lo) 64 rows, B(hi/lo) 128 rows, ROWW=68 word stride.
// BN1=false (gemm1): A=g_agg, C=g_h1, stats -> g_stats[0/128].
// BN1=true  (gemm2): A=relu(BN1(g_h1)), C=outp, stats -> g_stats[256/384].
// ---------------------------------------------------------------------------
#define ROWW 68                          // words per row (64 + 4 pad)
#define SMO_AH   0                       // 64*68*4   = 17408
#define SMO_AL   17408                   // +17408    = 34816
#define SMO_BH   34816                   // 128*68*4  = 34816 -> 69632
#define SMO_BL   69632                   // +34816    = 104448
#define SMO_BIAS 104448
#define SMO_SA   (SMO_BIAS + 512)
#define SMO_SC   (SMO_SA + 512)
#define SMO_SS   (SMO_SC + 512)
#define SMO_SQ   (SMO_SS + 512)
#define SMEM_GEMM (SMO_SQ + 512)         // 107008 bytes -> 2 CTAs/SM

__device__ __forceinline__ void split_h2(float x, float y,
                                         uint32_t& hi, uint32_t& lo) {
    __half hx = __float2half_rn(x), hy = __float2half_rn(y);
    __half lx = __float2half_rn(x - __half2float(hx));
    __half ly = __float2half_rn(y - __half2float(hy));
    hi = (uint32_t)__half_as_ushort(hx) | ((uint32_t)__half_as_ushort(hy) << 16);
    lo = (uint32_t)__half_as_ushort(lx) | ((uint32_t)__half_as_ushort(ly) << 16);
}

__device__ __forceinline__ void mma_f16(float* d, const uint32_t* a,
                                        uint32_t b0, uint32_t b1) {
    asm volatile(
        "mma.sync.aligned.m16n8k16.row.col.f32.f16.f16.f32 "
        "{%0,%1,%2,%3}, {%4,%5,%6,%7}, {%8,%9}, {%0,%1,%2,%3};"
        : "+f"(d[0]), "+f"(d[1]), "+f"(d[2]), "+f"(d[3])
        : "r"(a[0]), "r"(a[1]), "r"(a[2]), "r"(a[3]), "r"(b0), "r"(b1));
}

template <bool BN1>
__global__ void __launch_bounds__(256, 2)
gemm_mma(const float* __restrict__ W, const float* __restrict__ bias,
         const float* __restrict__ gamma, const float* __restrict__ beta,
         float* __restrict__ outp, int N, float invN) {
    const float* A  = BN1 ? g_h1 : g_agg;
    float* C        = BN1 ? outp : g_h1;
    float* statSum  = BN1 ? (g_stats + 256) : g_stats;
    float* statSq   = BN1 ? (g_stats + 384) : (g_stats + 128);

    extern __shared__ __align__(16) char smem[];
    uint32_t* Ah = (uint32_t*)(smem + SMO_AH);
    uint32_t* Al = (uint32_t*)(smem + SMO_AL);
    uint32_t* Bh = (uint32_t*)(smem + SMO_BH);
    uint32_t* Bl = (uint32_t*)(smem + SMO_BL);
    float* sbias = (float*)(smem + SMO_BIAS);
    float* s_a   = (float*)(smem + SMO_SA);
    float* s_c   = (float*)(smem + SMO_SC);
    float* sS    = (float*)(smem + SMO_SS);
    float* sQ    = (float*)(smem + SMO_SQ);

    int tid = threadIdx.x, wid = tid >> 5, lane = tid & 31;
    int wr = wid >> 2;        // 0..1 : rows wr*32 .. +32
    int wc = wid & 3;         // 0..3 : cols wc*32 .. +32
    int gid = lane >> 2;      // 0..7
    int tig = lane & 3;       // 0..3
    int m0 = blockIdx.x * 64;

    if (tid < 128) {
        sbias[tid] = bias[tid];
        sS[tid] = 0.f;
        sQ[tid] = 0.f;
        if (BN1) {
            float mu  = g_stats[tid] * invN;
            float var = g_stats[128 + tid] * invN - mu * mu;
            float a = gamma[tid] * rsqrtf(var + 1e-5f);
            s_a[tid] = a;
            s_c[tid] = beta[tid] - mu * a;
        }
    }
    __syncthreads();

    // ---- load + split A tile (64 rows x 32 float4 = 8 iters) ----
#pragma unroll
    for (int it = 0; it < 8; ++it) {
        int idx = tid + it * 256;        // 0..2047
        int row = idx >> 5;              // 0..63
        int kq  = idx & 31;              // float4 index 0..31
        int gm = m0 + row; if (gm >= N) gm = N - 1;
        float4 v = *(const float4*)(A + (size_t)gm * 128 + kq * 4);
        if (BN1) {
            int k0 = kq * 4;
            v.x = fmaxf(fmaf(v.x, s_a[k0 + 0], s_c[k0 + 0]), 0.f);
            v.y = fmaxf(fmaf(v.y, s_a[k0 + 1], s_c[k0 + 1]), 0.f);
            v.z = fmaxf(fmaf(v.z, s_a[k0 + 2], s_c[k0 + 2]), 0.f);
            v.w = fmaxf(fmaf(v.w, s_a[k0 + 3], s_c[k0 + 3]), 0.f);
        }
        uint32_t h0, l0, h1, l1;
        split_h2(v.x, v.y, h0, l0);
        split_h2(v.z, v.w, h1, l1);
        int o = row * ROWW + kq * 2;
        *(uint2*)(Ah + o) = make_uint2(h0, h1);
        *(uint2*)(Al + o) = make_uint2(l0, l1);
    }
    // ---- load + split W (128 rows) ----
#pragma unroll
    for (int it = 0; it < 16; ++it) {
        int idx = tid + it * 256;
        int row = idx >> 5;              // n
        int kq  = idx & 31;
        float4 v = *(const float4*)(W + (size_t)row * 128 + kq * 4);
        uint32_t h0, l0, h1, l1;
        split_h2(v.x, v.y, h0, l0);
        split_h2(v.z, v.w, h1, l1);
        int o = row * ROWW + kq * 2;
        *(uint2*)(Bh + o) = make_uint2(h0, h1);
        *(uint2*)(Bl + o) = make_uint2(l0, l1);
    }
    __syncthreads();

    // ---- mainloop: 8 K-chunks of 16; warp tile 32x32 ----
    float acc[2][4][4];
#pragma unroll
    for (int mt = 0; mt < 2; ++mt)
#pragma unroll
        for (int nt = 0; nt < 4; ++nt)
#pragma unroll
            for (int r = 0; r < 4; ++r) acc[mt][nt][r] = 0.f;

#pragma unroll
    for (int ks = 0; ks < 8; ++ks) {
        int kw0 = ks * 8;  // word offset of this K-chunk
        uint32_t ahi[2][4], alo[2][4];
#pragma unroll
        for (int mt = 0; mt < 2; ++mt) {
            int r0 = wr * 32 + mt * 16 + gid;
            ahi[mt][0] = Ah[r0 * ROWW + kw0 + tig];
            ahi[mt][1] = Ah[(r0 + 8) * ROWW + kw0 + tig];
            ahi[mt][2] = Ah[r0 * ROWW + kw0 + tig + 4];
            ahi[mt][3] = Ah[(r0 + 8) * ROWW + kw0 + tig + 4];
            alo[mt][0] = Al[r0 * ROWW + kw0 + tig];
            alo[mt][1] = Al[(r0 + 8) * ROWW + kw0 + tig];
            alo[mt][2] = Al[r0 * ROWW + kw0 + tig + 4];
            alo[mt][3] = Al[(r0 + 8) * ROWW + kw0 + tig + 4];
        }
#pragma unroll
        for (int nt = 0; nt < 4; ++nt) {
            int n = wc * 32 + nt * 8 + gid;
            uint32_t bh0 = Bh[n * ROWW + kw0 + tig];
            uint32_t bh1 = Bh[n * ROWW + kw0 + tig + 4];
            uint32_t bl0 = Bl[n * ROWW + kw0 + tig];
            uint32_t bl1 = Bl[n * ROWW + kw0 + tig + 4];
#pragma unroll
            for (int mt = 0; mt < 2; ++mt) {
                mma_f16(acc[mt][nt], ahi[mt], bh0, bh1);
                mma_f16(acc[mt][nt], ahi[mt], bl0, bl1);
                mma_f16(acc[mt][nt], alo[mt], bh0, bh1);
            }
        }
    }

    // ---- epilogue: bias add, store, fused column stats ----
    float ls[8], lq[8];
#pragma unroll
    for (int i = 0; i < 8; ++i) { ls[i] = 0.f; lq[i] = 0.f; }

#pragma unroll
    for (int mt = 0; mt < 2; ++mt) {
        int grow0 = m0 + wr * 32 + mt * 16 + gid;
        int grow1 = grow0 + 8;
        bool v0 = grow0 < N, v1 = grow1 < N;
#pragma unroll
        for (int nt = 0; nt < 4; ++nt) {
            int gcol = wc * 32 + nt * 8 + tig * 2;
            float d0 = acc[mt][nt][0] + sbias[gcol];
            float d1 = acc[mt][nt][1] + sbias[gcol + 1];
            float d2 = acc[mt][nt][2] + sbias[gcol];
            float d3 = acc[mt][nt][3] + sbias[gcol + 1];
            if (v0) {
                *(float2*)(C + (size_t)grow0 * 128 + gcol) = make_float2(d0, d1);
                ls[nt * 2]     += d0; lq[nt * 2]     = fmaf(d0, d0, lq[nt * 2]);
                ls[nt * 2 + 1] += d1; lq[nt * 2 + 1] = fmaf(d1, d1, lq[nt * 2 + 1]);
            }
            if (v1) {
                *(float2*)(C + (size_t)grow1 * 128 + gcol) = make_float2(d2, d3);
                ls[nt * 2]     += d2; lq[nt * 2]     = fmaf(d2, d2, lq[nt * 2]);
                ls[nt * 2 + 1] += d3; lq[nt * 2 + 1] = fmaf(d3, d3, lq[nt * 2 + 1]);
            }
        }
    }
    // reduce across the 8 row-owning lanes (gid) of the warp
#pragma unroll
    for (int d = 4; d < 32; d <<= 1) {
#pragma unroll
        for (int i = 0; i < 8; ++i) {
            ls[i] += __shfl_xor_sync(0xFFFFFFFFu, ls[i], d);
            lq[i] += __shfl_xor_sync(0xFFFFFFFFu, lq[i], d);
        }
    }
    if (gid == 0) {
#pragma unroll
        for (int i = 0; i < 8; ++i) {
            int col = wc * 32 + (i >> 1) * 8 + tig * 2 + (i & 1);
            atomicAdd(&sS[col], ls[i]);
            atomicAdd(&sQ[col], lq[i]);
        }
    }
    __syncthreads();
    if (tid < 128) {
        atomicAdd(&statSum[tid], sS[tid]);
        atomicAdd(&statSq[tid],  sQ[tid]);
    }
}

// out = relu(BN2(out)), BN2 affine computed per block from g_stats.
__global__ void __launch_bounds__(256)
bnrelu_kernel(float* __restrict__ out,
              const float* __restrict__ gamma, const float* __restrict__ beta,
              int N, float invN) {
    __shared__ float s_a[128], s_c[128];
    int tid = threadIdx.x;
    if (tid < 128) {
        float mu  = g_stats[256 + tid] * invN;
        float var = g_stats[384 + tid] * invN - mu * mu;
        float a = gamma[tid] * rsqrtf(var + 1e-5f);
        s_a[tid] = a;
        s_c[tid] = beta[tid] - mu * a;
    }
    __syncthreads();
    int c4 = (tid & 31) << 2;
    float4 a4  = *(const float4*)(s_a + c4);
    float4 c4v = *(const float4*)(s_c + c4);
    int rows_per_iter = gridDim.x * (blockDim.x >> 5);
    int r = blockIdx.x * (blockDim.x >> 5) + (tid >> 5);
    float4* o4 = (float4*)out;
    for (; r < N; r += rows_per_iter) {
        size_t idx = (size_t)r * 32 + (tid & 31);
        float4 v = o4[idx];
        v.x = fmaxf(fmaf(v.x, a4.x, c4v.x), 0.f);
        v.y = fmaxf(fmaf(v.y, a4.y, c4v.y), 0.f);
        v.z = fmaxf(fmaf(v.z, a4.z, c4v.z), 0.f);
        v.w = fmaxf(fmaf(v.w, a4.w, c4v.w), 0.f);
        o4[idx] = v;
    }
}

// ---------------------------------------------------------------------------
extern "C" void kernel_launch(void* const* d_in, const int* in_sizes, int n_in,
                              void* d_out, int out_size) {
    const float* x   = (const float*)d_in[0];
    const void*  ei  = d_in[1];
    const float* eps = (const float*)d_in[2];
    const float* W1  = (const float*)d_in[3];
    const float* b1  = (const float*)d_in[4];
    const float* g1  = (const float*)d_in[5];
    const float* be1 = (const float*)d_in[6];
    const float* W2  = (const float*)d_in[7];
    const float* b2  = (const float*)d_in[8];
    const float* g2  = (const float*)d_in[9];
    const float* be2 = (const float*)d_in[10];

    int N = in_sizes[0] / 128;
    int E = in_sizes[1] / 2;
    if (E > MAXE) E = MAXE;
    float* out = (float*)d_out;
    float invN = 1.f / (float)N;

    cudaFuncSetAttribute(gemm_mma<false>,
                         cudaFuncAttributeMaxDynamicSharedMemorySize, SMEM_GEMM);
    cudaFuncSetAttribute(gemm_mma<true>,
                         cudaFuncAttributeMaxDynamicSharedMemorySize, SMEM_GEMM);

    init_kernel<<<(N + 255) / 256, 256>>>((const int*)ei, E, N);
    bucket_kernel<<<(E + 511) / 512, 256>>>(ei, E);

    int ablocks = (N * 32 + 255) / 256;
    aggregate_kernel<<<ablocks, 256>>>(x, eps, N);

    int gblocks = (N + 63) / 64;
    gemm_mma<false><<<gblocks, 256, SMEM_GEMM>>>(W1, b1, nullptr, nullptr,
                                                 nullptr, N, invN);
    gemm_mma<true><<<gblocks, 256, SMEM_GEMM>>>(W2, b2, g1, be1,
                                                out, N, invN);
    bnrelu_kernel<<<592, 256>>>(out, g2, be2, N, invN);
}

// round 15
// speedup vs baseline: 1.1212x; 1.0035x over previous
#include <cuda_runtime.h>
#include <cuda_fp16.h>
#include <cstdint>

// ---------------------------------------------------------------------------
// GIN block. 7-kernel pipeline (bucket CSR; W pre-split; agg pre-split):
//   init -> wsplit (W1/W2 -> fp16 hi/lo, once) -> bucket ->
//   aggregate (CSR gather, writes fp16 hi/lo directly) ->
//   gemm1 (pure-copy prologue, mma 3xFP16 m16n8k16, fused BN1 stats) ->
//   gemm2 (BN1+ReLU fold + split on load, fused BN2 stats) -> bnrelu.
// R14 ncu: GEMM not memory- or tensor-bound; serial cvt prologue was the
// wall -> hoist all W splitting (once) and gemm1's A splitting (into the
// high-occupancy aggregate kernel).
// ---------------------------------------------------------------------------

#define MAXN 50048
#define MAXE 1600000
#define BK   64         // bucket slots per node (Poisson(16) max deg ~40)

__device__ __align__(16) uint32_t g_aggh[MAXN * 64];  // fp16x2 hi words
__device__ __align__(16) uint32_t g_aggl[MAXN * 64];  // fp16x2 lo words
__device__ __align__(16) float    g_h1[MAXN * 128];
__device__ __align__(16) uint32_t g_w1h[128 * 64], g_w1l[128 * 64];
__device__ __align__(16) uint32_t g_w2h[128 * 64], g_w2l[128 * 64];
__device__ float g_stats[512];   // [sum1, sumsq1, sum2, sumsq2] x 128
__device__ int   g_deg[MAXN];
__device__ int   g_bucket[MAXN * BK];
__device__ int   g_ovf[2 * MAXE];  // (dst, src) pairs for rank >= BK
__device__ int   g_ovfcnt;
__device__ int   g_is64;

__device__ __forceinline__ void split_h2(float x, float y,
                                         uint32_t& hi, uint32_t& lo) {
    __half hx = __float2half_rn(x), hy = __float2half_rn(y);
    __half lx = __float2half_rn(x - __half2float(hx));
    __half ly = __float2half_rn(y - __half2float(hy));
    hi = (uint32_t)__half_as_ushort(hx) | ((uint32_t)__half_as_ushort(hy) << 16);
    lo = (uint32_t)__half_as_ushort(lx) | ((uint32_t)__half_as_ushort(ly) << 16);
}

// ---------------------------------------------------------------------------
__global__ void init_kernel(const int* __restrict__ ei32, int E, int N) {
    int i = blockIdx.x * blockDim.x + threadIdx.x;
    if (i < N) g_deg[i] = 0;
    if (i < 512) g_stats[i] = 0.f;
    if (i == 0) g_ovfcnt = 0;
    if (blockIdx.x == 0) {
        __shared__ int nz;
        if (threadIdx.x == 0) nz = 0;
        __syncthreads();
        int pairs = E < 2048 ? E : 2048;
        int cnt = 0;
        for (int j = threadIdx.x; j < pairs; j += blockDim.x)
            if (ei32[2 * j + 1] != 0) cnt++;
        if (cnt) atomicOr(&nz, 1);
        __syncthreads();
        if (threadIdx.x == 0) g_is64 = (nz == 0) ? 1 : 0;
    }
}

// Split W1 and W2 (16384 floats each) into fp16 hi/lo word arrays, once.
__global__ void wsplit_kernel(const float* __restrict__ W1,
                              const float* __restrict__ W2) {
    int i = blockIdx.x * blockDim.x + threadIdx.x;  // 0..8191 (float4 units)
    int m = i >> 12;                                 // 0: W1, 1: W2
    int j = i & 4095;                                // float4 index in matrix
    const float* W = m ? W2 : W1;
    uint32_t* Hh = m ? g_w2h : g_w1h;
    uint32_t* Hl = m ? g_w2l : g_w1l;
    float4 v = ((const float4*)W)[j];
    uint32_t h0, l0, h1, l1;
    split_h2(v.x, v.y, h0, l0);
    split_h2(v.z, v.w, h1, l1);
    ((uint2*)Hh)[j] = make_uint2(h0, h1);
    ((uint2*)Hl)[j] = make_uint2(l0, l1);
}

__device__ __forceinline__ int load_idx(const void* ei, long long i) {
    return g_is64 ? (int)((const long long*)ei)[i] : ((const int*)ei)[i];
}

// Histogram + direct bucket write. 2 edges per thread.
__global__ void bucket_kernel(const void* __restrict__ ei, int E) {
    int i = (blockIdx.x * blockDim.x + threadIdx.x) * 2;
#pragma unroll
    for (int t = 0; t < 2; ++t, ++i) {
        if (i >= E) return;
        int src = load_idx(ei, i);
        int dst = load_idx(ei, (long long)E + i);
        int r = atomicAdd(&g_deg[dst], 1);
        if (r < BK) {
            g_bucket[dst * BK + r] = src;
        } else {
            int o = atomicAdd(&g_ovfcnt, 1);
            g_ovf[2 * o] = dst;
            g_ovf[2 * o + 1] = src;
        }
    }
}

// One warp per node: acc = (1+eps)*x[node] + sum of bucketed neighbor rows.
// Writes the fp16 hi/lo split DIRECTLY (gemm1's A prologue becomes a copy).
__global__ void aggregate_kernel(const float* __restrict__ x,
                                 const float* __restrict__ eps, int N) {
    int w = (int)((blockIdx.x * blockDim.x + threadIdx.x) >> 5);
    if (w >= N) return;
    int lane = threadIdx.x & 31;
    const float4* x4 = (const float4*)x;
    float s = 1.f + eps[0];
    float4 acc = x4[(size_t)w * 32 + lane];
    acc.x *= s; acc.y *= s; acc.z *= s; acc.w *= s;
    float4 acc2 = make_float4(0.f, 0.f, 0.f, 0.f);
    int deg = g_deg[w];
    int cnt = deg < BK ? deg : BK;
    const int* bk = g_bucket + (size_t)w * BK;
    int j = 0;
    for (; j + 3 < cnt; j += 4) {
        int s0 = bk[j + 0];
        int s1 = bk[j + 1];
        int s2 = bk[j + 2];
        int s3 = bk[j + 3];
        float4 v0 = x4[(size_t)s0 * 32 + lane];
        float4 v1 = x4[(size_t)s1 * 32 + lane];
        float4 v2 = x4[(size_t)s2 * 32 + lane];
        float4 v3 = x4[(size_t)s3 * 32 + lane];
        acc.x  += v0.x + v1.x; acc.y  += v0.y + v1.y;
        acc.z  += v0.z + v1.z; acc.w  += v0.w + v1.w;
        acc2.x += v2.x + v3.x; acc2.y += v2.y + v3.y;
        acc2.z += v2.z + v3.z; acc2.w += v2.w + v3.w;
    }
    for (; j < cnt; j++) {
        float4 v0 = x4[(size_t)bk[j] * 32 + lane];
        acc.x += v0.x; acc.y += v0.y; acc.z += v0.z; acc.w += v0.w;
    }
    if (deg > BK) {  // drain overflow entries for this node (rare/none)
        int oc = g_ovfcnt;
        for (int i = 0; i < oc; ++i) {
            if (g_ovf[2 * i] == w) {
                float4 v0 = x4[(size_t)g_ovf[2 * i + 1] * 32 + lane];
                acc.x += v0.x; acc.y += v0.y; acc.z += v0.z; acc.w += v0.w;
            }
        }
    }
    acc.x += acc2.x; acc.y += acc2.y; acc.z += acc2.z; acc.w += acc2.w;
    uint32_t h0, l0, h1, l1;
    split_h2(acc.x, acc.y, h0, l0);
    split_h2(acc.z, acc.w, h1, l1);
    ((uint2*)g_aggh)[(size_t)w * 32 + lane] = make_uint2(h0, h1);
    ((uint2*)g_aggl)[(size_t)w * 32 + lane] = make_uint2(l0, l1);
}

// ---------------------------------------------------------------------------
// 3xFP16-split tensor-core GEMM (m16n8k16): D = Ain @ W^T + bias.
// CTA tile 64x128, 2 CTAs/SM, 8 warps = 2 row-groups(32) x 4 col-groups(32).
// W always pre-split (pure smem copy). gemm1: A pre-split too (pure copy).
// gemm2: A = relu(BN1(g_h1)) folded + split on load.
// ---------------------------------------------------------------------------
#define ROWW 68                          // words per row (64 + 4 pad)
#define SMO_AH   0                       // 64*68*4   = 17408
#define SMO_AL   17408                   // +17408    = 34816
#define SMO_BH   34816                   // 128*68*4  = 34816 -> 69632
#define SMO_BL   69632                   // +34816    = 104448
#define SMO_BIAS 104448
#define SMO_SA   (SMO_BIAS + 512)
#define SMO_SC   (SMO_SA + 512)
#define SMO_SS   (SMO_SC + 512)
#define SMO_SQ   (SMO_SS + 512)
#define SMEM_GEMM (SMO_SQ + 512)         // 107008 bytes -> 2 CTAs/SM

__device__ __forceinline__ void mma_f16(float* d, const uint32_t* a,
                                        uint32_t b0, uint32_t b1) {
    asm volatile(
        "mma.sync.aligned.m16n8k16.row.col.f32.f16.f16.f32 "
        "{%0,%1,%2,%3}, {%4,%5,%6,%7}, {%8,%9}, {%0,%1,%2,%3};"
        : "+f"(d[0]), "+f"(d[1]), "+f"(d[2]), "+f"(d[3])
        : "r"(a[0]), "r"(a[1]), "r"(a[2]), "r"(a[3]), "r"(b0), "r"(b1));
}

template <bool BN1>
__global__ void __launch_bounds__(256, 2)
gemm_mma(const float* __restrict__ bias,
         const float* __restrict__ gamma, const float* __restrict__ beta,
         float* __restrict__ outp, int N, float invN) {
    float* C        = BN1 ? outp : g_h1;
    float* statSum  = BN1 ? (g_stats + 256) : g_stats;
    float* statSq   = BN1 ? (g_stats + 384) : (g_stats + 128);
    const uint32_t* Wh = BN1 ? g_w2h : g_w1h;
    const uint32_t* Wl = BN1 ? g_w2l : g_w1l;

    extern __shared__ __align__(16) char smem[];
    uint32_t* Ah = (uint32_t*)(smem + SMO_AH);
    uint32_t* Al = (uint32_t*)(smem + SMO_AL);
    uint32_t* Bh = (uint32_t*)(smem + SMO_BH);
    uint32_t* Bl = (uint32_t*)(smem + SMO_BL);
    float* sbias = (float*)(smem + SMO_BIAS);
    float* s_a   = (float*)(smem + SMO_SA);
    float* s_c   = (float*)(smem + SMO_SC);
    float* sS    = (float*)(smem + SMO_SS);
    float* sQ    = (float*)(smem + SMO_SQ);

    int tid = threadIdx.x, wid = tid >> 5, lane = tid & 31;
    int wr = wid >> 2;        // 0..1 : rows wr*32 .. +32
    int wc = wid & 3;         // 0..3 : cols wc*32 .. +32
    int gid = lane >> 2;      // 0..7
    int tig = lane & 3;       // 0..3
    int m0 = blockIdx.x * 64;

    if (tid < 128) {
        sbias[tid] = bias[tid];
        sS[tid] = 0.f;
        sQ[tid] = 0.f;
        if (BN1) {
            float mu  = g_stats[tid] * invN;
            float var = g_stats[128 + tid] * invN - mu * mu;
            float a = gamma[tid] * rsqrtf(var + 1e-5f);
            s_a[tid] = a;
            s_c[tid] = beta[tid] - mu * a;
        }
    }
    __syncthreads();

    // ---- A tile (64 rows) ----
    if (BN1) {
        // load fp32 h1, fold BN1+ReLU, split
#pragma unroll
        for (int it = 0; it < 8; ++it) {
            int idx = tid + it * 256;        // 0..2047
            int row = idx >> 5;              // 0..63
            int kq  = idx & 31;              // float4 index 0..31
            int gm = m0 + row; if (gm >= N) gm = N - 1;
            float4 v = *(const float4*)(g_h1 + (size_t)gm * 128 + kq * 4);
            int k0 = kq * 4;
            v.x = fmaxf(fmaf(v.x, s_a[k0 + 0], s_c[k0 + 0]), 0.f);
            v.y = fmaxf(fmaf(v.y, s_a[k0 + 1], s_c[k0 + 1]), 0.f);
            v.z = fmaxf(fmaf(v.z, s_a[k0 + 2], s_c[k0 + 2]), 0.f);
            v.w = fmaxf(fmaf(v.w, s_a[k0 + 3], s_c[k0 + 3]), 0.f);
            uint32_t h0, l0, h1, l1;
            split_h2(v.x, v.y, h0, l0);
            split_h2(v.z, v.w, h1, l1);
            int o = row * ROWW + kq * 2;
            *(uint2*)(Ah + o) = make_uint2(h0, h1);
            *(uint2*)(Al + o) = make_uint2(l0, l1);
        }
    } else {
        // pure copy of pre-split agg: 64 rows x 16 uint4 = 1024 -> 4 iters
#pragma unroll
        for (int it = 0; it < 4; ++it) {
            int idx = tid + it * 256;        // 0..1023
            int row = idx >> 4;              // 0..63
            int c   = idx & 15;              // uint4 index 0..15
            int gm = m0 + row; if (gm >= N) gm = N - 1;
            uint4 h = *(const uint4*)(g_aggh + (size_t)gm * 64 + c * 4);
            uint4 l = *(const uint4*)(g_aggl + (size_t)gm * 64 + c * 4);
            int o = row * ROWW + c * 4;
            *(uint4*)(Ah + o) = h;
            *(uint4*)(Al + o) = l;
        }
    }
    // ---- W tile: pure copy of pre-split weights (128 rows x 16 uint4) ----
#pragma unroll
    for (int it = 0; it < 8; ++it) {
        int idx = tid + it * 256;            // 0..2047
        int row = idx >> 4;                  // 0..127
        int c   = idx & 15;
        uint4 h = *(const uint4*)(Wh + (size_t)row * 64 + c * 4);
        uint4 l = *(const uint4*)(Wl + (size_t)row * 64 + c * 4);
        int o = row * ROWW + c * 4;
        *(uint4*)(Bh + o) = h;
        *(uint4*)(Bl + o) = l;
    }
    __syncthreads();

    // ---- mainloop: 8 K-chunks of 16; warp tile 32x32 ----
    float acc[2][4][4];
#pragma unroll
    for (int mt = 0; mt < 2; ++mt)
#pragma unroll
        for (int nt = 0; nt < 4; ++nt)
#pragma unroll
            for (int r = 0; r < 4; ++r) acc[mt][nt][r] = 0.f;

#pragma unroll
    for (int ks = 0; ks < 8; ++ks) {
        int kw0 = ks * 8;  // word offset of this K-chunk
        uint32_t ahi[2][4], alo[2][4];
#pragma unroll
        for (int mt = 0; mt < 2; ++mt) {
            int r0 = wr * 32 + mt * 16 + gid;
            ahi[mt][0] = Ah[r0 * ROWW + kw0 + tig];
            ahi[mt][1] = Ah[(r0 + 8) * ROWW + kw0 + tig];
            ahi[mt][2] = Ah[r0 * ROWW + kw0 + tig + 4];
            ahi[mt][3] = Ah[(r0 + 8) * ROWW + kw0 + tig + 4];
            alo[mt][0] = Al[r0 * ROWW + kw0 + tig];
            alo[mt][1] = Al[(r0 + 8) * ROWW + kw0 + tig];
            alo[mt][2] = Al[r0 * ROWW + kw0 + tig + 4];
            alo[mt][3] = Al[(r0 + 8) * ROWW + kw0 + tig + 4];
        }
#pragma unroll
        for (int nt = 0; nt < 4; ++nt) {
            int n = wc * 32 + nt * 8 + gid;
            uint32_t bh0 = Bh[n * ROWW + kw0 + tig];
            uint32_t bh1 = Bh[n * ROWW + kw0 + tig + 4];
            uint32_t bl0 = Bl[n * ROWW + kw0 + tig];
            uint32_t bl1 = Bl[n * ROWW + kw0 + tig + 4];
#pragma unroll
            for (int mt = 0; mt < 2; ++mt) {
                mma_f16(acc[mt][nt], ahi[mt], bh0, bh1);
                mma_f16(acc[mt][nt], ahi[mt], bl0, bl1);
                mma_f16(acc[mt][nt], alo[mt], bh0, bh1);
            }
        }
    }

    // ---- epilogue: bias add, store, fused column stats ----
    float ls[8], lq[8];
#pragma unroll
    for (int i = 0; i < 8; ++i) { ls[i] = 0.f; lq[i] = 0.f; }

#pragma unroll
    for (int mt = 0; mt < 2; ++mt) {
        int grow0 = m0 + wr * 32 + mt * 16 + gid;
        int grow1 = grow0 + 8;
        bool v0 = grow0 < N, v1 = grow1 < N;
#pragma unroll
        for (int nt = 0; nt < 4; ++nt) {
            int gcol = wc * 32 + nt * 8 + tig * 2;
            float d0 = acc[mt][nt][0] + sbias[gcol];
            float d1 = acc[mt][nt][1] + sbias[gcol + 1];
            float d2 = acc[mt][nt][2] + sbias[gcol];
            float d3 = acc[mt][nt][3] + sbias[gcol + 1];
            if (v0) {
                *(float2*)(C + (size_t)grow0 * 128 + gcol) = make_float2(d0, d1);
                ls[nt * 2]     += d0; lq[nt * 2]     = fmaf(d0, d0, lq[nt * 2]);
                ls[nt * 2 + 1] += d1; lq[nt * 2 + 1] = fmaf(d1, d1, lq[nt * 2 + 1]);
            }
            if (v1) {
                *(float2*)(C + (size_t)grow1 * 128 + gcol) = make_float2(d2, d3);
                ls[nt * 2]     += d2; lq[nt * 2]     = fmaf(d2, d2, lq[nt * 2]);
                ls[nt * 2 + 1] += d3; lq[nt * 2 + 1] = fmaf(d3, d3, lq[nt * 2 + 1]);
            }
        }
    }
    // reduce across the 8 row-owning lanes (gid) of the warp
#pragma unroll
    for (int d = 4; d < 32; d <<= 1) {
#pragma unroll
        for (int i = 0; i < 8; ++i) {
            ls[i] += __shfl_xor_sync(0xFFFFFFFFu, ls[i], d);
            lq[i] += __shfl_xor_sync(0xFFFFFFFFu, lq[i], d);
        }
    }
    if (gid == 0) {
#pragma unroll
        for (int i = 0; i < 8; ++i) {
            int col = wc * 32 + (i >> 1) * 8 + tig * 2 + (i & 1);
            atomicAdd(&sS[col], ls[i]);
            atomicAdd(&sQ[col], lq[i]);
        }
    }
    __syncthreads();
    if (tid < 128) {
        atomicAdd(&statSum[tid], sS[tid]);
        atomicAdd(&statSq[tid],  sQ[tid]);
    }
}

// out = relu(BN2(out)), BN2 affine computed per block from g_stats.
__global__ void __launch_bounds__(256)
bnrelu_kernel(float* __restrict__ out,
              const float* __restrict__ gamma, const float* __restrict__ beta,
              int N, float invN) {
    __shared__ float s_a[128], s_c[128];
    int tid = threadIdx.x;
    if (tid < 128) {
        float mu  = g_stats[256 + tid] * invN;
        float var = g_stats[384 + tid] * invN - mu * mu;
        float a = gamma[tid] * rsqrtf(var + 1e-5f);
        s_a[tid] = a;
        s_c[tid] = beta[tid] - mu * a;
    }
    __syncthreads();
    int c4 = (tid & 31) << 2;
    float4 a4  = *(const float4*)(s_a + c4);
    float4 c4v = *(const float4*)(s_c + c4);
    int rows_per_iter = gridDim.x * (blockDim.x >> 5);
    int r = blockIdx.x * (blockDim.x >> 5) + (tid >> 5);
    float4* o4 = (float4*)out;
    for (; r < N; r += rows_per_iter) {
        size_t idx = (size_t)r * 32 + (tid & 31);
        float4 v = o4[idx];
        v.x = fmaxf(fmaf(v.x, a4.x, c4v.x), 0.f);
        v.y = fmaxf(fmaf(v.y, a4.y, c4v.y), 0.f);
        v.z = fmaxf(fmaf(v.z, a4.z, c4v.z), 0.f);
        v.w = fmaxf(fmaf(v.w, a4.w, c4v.w), 0.f);
        o4[idx] = v;
    }
}

// ---------------------------------------------------------------------------
extern "C" void kernel_launch(void* const* d_in, const int* in_sizes, int n_in,
                              void* d_out, int out_size) {
    const float* x   = (const float*)d_in[0];
    const void*  ei  = d_in[1];
    const float* eps = (const float*)d_in[2];
    const float* W1  = (const float*)d_in[3];
    const float* b1  = (const float*)d_in[4];
    const float* g1  = (const float*)d_in[5];
    const float* be1 = (const float*)d_in[6];
    const float* W2  = (const float*)d_in[7];
    const float* b2  = (const float*)d_in[8];
    const float* g2  = (const float*)d_in[9];
    const float* be2 = (const float*)d_in[10];

    int N = in_sizes[0] / 128;
    int E = in_sizes[1] / 2;
    if (E > MAXE) E = MAXE;
    float* out = (float*)d_out;
    float invN = 1.f / (float)N;

    cudaFuncSetAttribute(gemm_mma<false>,
                         cudaFuncAttributeMaxDynamicSharedMemorySize, SMEM_GEMM);
    cudaFuncSetAttribute(gemm_mma<true>,
                         cudaFuncAttributeMaxDynamicSharedMemorySize, SMEM_GEMM);

    init_kernel<<<(N + 255) / 256, 256>>>((const int*)ei, E, N);
    wsplit_kernel<<<32, 256>>>(W1, W2);
    bucket_kernel<<<(E + 511) / 512, 256>>>(ei, E);

    int ablocks = (N * 32 + 255) / 256;
    aggregate_kernel<<<ablocks, 256>>>(x, eps, N);

    int gblocks = (N + 63) / 64;
    gemm_mma<false><<<gblocks, 256, SMEM_GEMM>>>(b1, nullptr, nullptr,
                                                 nullptr, N, invN);
    gemm_mma<true><<<gblocks, 256, SMEM_GEMM>>>(b2, g1, be1, out, N, invN);
    bnrelu_kernel<<<592, 256>>>(out, g2, be2, N, invN);
}

// round 16
// speedup vs baseline: 1.2445x; 1.1100x over previous
#include <cuda_runtime.h>
#include <cuda_fp16.h>
#include <cstdint>

// ---------------------------------------------------------------------------
// GIN block. 7-kernel pipeline (bucket CSR; W/agg pre-split; persistent GEMM):
//   init -> wsplit -> bucket -> aggregate (gather, writes fp16 hi/lo) ->
//   gemm1 (persistent, W loaded once, fused BN1 stats) ->
//   gemm2 (persistent, BN1 fold+split on load, fused BN2 stats) -> bnrelu.
// R15 lesson: GEMM prologue cvt was NOT the wall; serial phases + W recopy
// were -> persistent CTAs, W resident across tiles.
// Aggregate measured AT the LTS gather roofline (~36us) - leave algorithm.
// ---------------------------------------------------------------------------

#define MAXN 50048
#define MAXE 1600000
#define BK   64         // bucket slots per node (Poisson(16) max deg ~40)

__device__ __align__(16) uint32_t g_aggh[MAXN * 64];  // fp16x2 hi words
__device__ __align__(16) uint32_t g_aggl[MAXN * 64];  // fp16x2 lo words
__device__ __align__(16) float    g_h1[MAXN * 128];
__device__ __align__(16) uint32_t g_w1h[128 * 64], g_w1l[128 * 64];
__device__ __align__(16) uint32_t g_w2h[128 * 64], g_w2l[128 * 64];
__device__ float g_stats[512];   // [sum1, sumsq1, sum2, sumsq2] x 128
__device__ int   g_deg[MAXN];
__device__ int   g_bucket[MAXN * BK];
__device__ int   g_ovf[2 * MAXE];  // (dst, src) pairs for rank >= BK
__device__ int   g_ovfcnt;
__device__ int   g_is64;

__device__ __forceinline__ void split_h2(float x, float y,
                                         uint32_t& hi, uint32_t& lo) {
    __half hx = __float2half_rn(x), hy = __float2half_rn(y);
    __half lx = __float2half_rn(x - __half2float(hx));
    __half ly = __float2half_rn(y - __half2float(hy));
    hi = (uint32_t)__half_as_ushort(hx) | ((uint32_t)__half_as_ushort(hy) << 16);
    lo = (uint32_t)__half_as_ushort(lx) | ((uint32_t)__half_as_ushort(ly) << 16);
}

// ---------------------------------------------------------------------------
__global__ void init_kernel(const int* __restrict__ ei32, int E, int N) {
    int i = blockIdx.x * blockDim.x + threadIdx.x;
    if (i < N) g_deg[i] = 0;
    if (i < 512) g_stats[i] = 0.f;
    if (i == 0) g_ovfcnt = 0;
    if (blockIdx.x == 0) {
        __shared__ int nz;
        if (threadIdx.x == 0) nz = 0;
        __syncthreads();
        int pairs = E < 2048 ? E : 2048;
        int cnt = 0;
        for (int j = threadIdx.x; j < pairs; j += blockDim.x)
            if (ei32[2 * j + 1] != 0) cnt++;
        if (cnt) atomicOr(&nz, 1);
        __syncthreads();
        if (threadIdx.x == 0) g_is64 = (nz == 0) ? 1 : 0;
    }
}

// Split W1 and W2 (16384 floats each) into fp16 hi/lo word arrays, once.
__global__ void wsplit_kernel(const float* __restrict__ W1,
                              const float* __restrict__ W2) {
    int i = blockIdx.x * blockDim.x + threadIdx.x;  // 0..8191 (float4 units)
    int m = i >> 12;                                 // 0: W1, 1: W2
    int j = i & 4095;                                // float4 index in matrix
    const float* W = m ? W2 : W1;
    uint32_t* Hh = m ? g_w2h : g_w1h;
    uint32_t* Hl = m ? g_w2l : g_w1l;
    float4 v = ((const float4*)W)[j];
    uint32_t h0, l0, h1, l1;
    split_h2(v.x, v.y, h0, l0);
    split_h2(v.z, v.w, h1, l1);
    ((uint2*)Hh)[j] = make_uint2(h0, h1);
    ((uint2*)Hl)[j] = make_uint2(l0, l1);
}

__device__ __forceinline__ int load_idx(const void* ei, long long i) {
    return g_is64 ? (int)((const long long*)ei)[i] : ((const int*)ei)[i];
}

// Histogram + direct bucket write. 2 edges per thread.
__global__ void bucket_kernel(const void* __restrict__ ei, int E) {
    int i = (blockIdx.x * blockDim.x + threadIdx.x) * 2;
#pragma unroll
    for (int t = 0; t < 2; ++t, ++i) {
        if (i >= E) return;
        int src = load_idx(ei, i);
        int dst = load_idx(ei, (long long)E + i);
        int r = atomicAdd(&g_deg[dst], 1);
        if (r < BK) {
            g_bucket[dst * BK + r] = src;
        } else {
            int o = atomicAdd(&g_ovfcnt, 1);
            g_ovf[2 * o] = dst;
            g_ovf[2 * o + 1] = src;
        }
    }
}

// One warp per node: acc = (1+eps)*x[node] + sum of bucketed neighbor rows.
// int4 index loads (bucket rows are 256B-aligned/contiguous); writes fp16
// hi/lo split directly so gemm1's A prologue is a pure copy.
__global__ void aggregate_kernel(const float* __restrict__ x,
                                 const float* __restrict__ eps, int N) {
    int w = (int)((blockIdx.x * blockDim.x + threadIdx.x) >> 5);
    if (w >= N) return;
    int lane = threadIdx.x & 31;
    const float4* x4 = (const float4*)x;
    float s = 1.f + eps[0];
    float4 acc = x4[(size_t)w * 32 + lane];
    acc.x *= s; acc.y *= s; acc.z *= s; acc.w *= s;
    float4 acc2 = make_float4(0.f, 0.f, 0.f, 0.f);
    int deg = g_deg[w];
    int cnt = deg < BK ? deg : BK;
    const int* bk = g_bucket + (size_t)w * BK;
    int j = 0;
    for (; j + 3 < cnt; j += 4) {
        int4 si = *(const int4*)(bk + j);
        float4 v0 = x4[(size_t)si.x * 32 + lane];
        float4 v1 = x4[(size_t)si.y * 32 + lane];
        float4 v2 = x4[(size_t)si.z * 32 + lane];
        float4 v3 = x4[(size_t)si.w * 32 + lane];
        acc.x  += v0.x + v1.x; acc.y  += v0.y + v1.y;
        acc.z  += v0.z + v1.z; acc.w  += v0.w + v1.w;
        acc2.x += v2.x + v3.x; acc2.y += v2.y + v3.y;
        acc2.z += v2.z + v3.z; acc2.w += v2.w + v3.w;
    }
    for (; j < cnt; j++) {
        float4 v0 = x4[(size_t)bk[j] * 32 + lane];
        acc.x += v0.x; acc.y += v0.y; acc.z += v0.z; acc.w += v0.w;
    }
    if (deg > BK) {  // drain overflow entries for this node (rare/none)
        int oc = g_ovfcnt;
        for (int i = 0; i < oc; ++i) {
            if (g_ovf[2 * i] == w) {
                float4 v0 = x4[(size_t)g_ovf[2 * i + 1] * 32 + lane];
                acc.x += v0.x; acc.y += v0.y; acc.z += v0.z; acc.w += v0.w;
            }
        }
    }
    acc.x += acc2.x; acc.y += acc2.y; acc.z += acc2.z; acc.w += acc2.w;
    uint32_t h0, l0, h1, l1;
    split_h2(acc.x, acc.y, h0, l0);
    split_h2(acc.z, acc.w, h1, l1);
    ((uint2*)g_aggh)[(size_t)w * 32 + lane] = make_uint2(h0, h1);
    ((uint2*)g_aggl)[(size_t)w * 32 + lane] = make_uint2(l0, l1);
}

// ---------------------------------------------------------------------------
// Persistent 3xFP16-split tensor-core GEMM (m16n8k16): D = Ain @ W^T + bias.
// Grid 296 = 2 CTAs/SM; each CTA loops row tiles (64 rows) with stride grid.
// W/bias/affine loaded ONCE per CTA; per tile only the 34.8KB A fill repeats.
// gemm1: A = pre-split agg (pure copy). gemm2: A = relu(BN1(g_h1)) + split.
// ---------------------------------------------------------------------------
#define ROWW 68                          // words per row (64 + 4 pad)
#define SMO_AH   0                       // 64*68*4   = 17408
#define SMO_AL   17408                   // +17408    = 34816
#define SMO_BH   34816                   // 128*68*4  = 34816 -> 69632
#define SMO_BL   69632                   // +34816    = 104448
#define SMO_BIAS 104448
#define SMO_SA   (SMO_BIAS + 512)
#define SMO_SC   (SMO_SA + 512)
#define SMO_SS   (SMO_SC + 512)
#define SMO_SQ   (SMO_SS + 512)
#define SMEM_GEMM (SMO_SQ + 512)         // 107008 bytes -> 2 CTAs/SM

__device__ __forceinline__ void mma_f16(float* d, const uint32_t* a,
                                        uint32_t b0, uint32_t b1) {
    asm volatile(
        "mma.sync.aligned.m16n8k16.row.col.f32.f16.f16.f32 "
        "{%0,%1,%2,%3}, {%4,%5,%6,%7}, {%8,%9}, {%0,%1,%2,%3};"
        : "+f"(d[0]), "+f"(d[1]), "+f"(d[2]), "+f"(d[3])
        : "r"(a[0]), "r"(a[1]), "r"(a[2]), "r"(a[3]), "r"(b0), "r"(b1));
}

template <bool BN1>
__global__ void __launch_bounds__(256, 2)
gemm_mma(const float* __restrict__ bias,
         const float* __restrict__ gamma, const float* __restrict__ beta,
         float* __restrict__ outp, int N, float invN, int tiles) {
    float* C        = BN1 ? outp : g_h1;
    float* statSum  = BN1 ? (g_stats + 256) : g_stats;
    float* statSq   = BN1 ? (g_stats + 384) : (g_stats + 128);
    const uint32_t* Wh = BN1 ? g_w2h : g_w1h;
    const uint32_t* Wl = BN1 ? g_w2l : g_w1l;

    extern __shared__ __align__(16) char smem[];
    uint32_t* Ah = (uint32_t*)(smem + SMO_AH);
    uint32_t* Al = (uint32_t*)(smem + SMO_AL);
    uint32_t* Bh = (uint32_t*)(smem + SMO_BH);
    uint32_t* Bl = (uint32_t*)(smem + SMO_BL);
    float* sbias = (float*)(smem + SMO_BIAS);
    float* s_a   = (float*)(smem + SMO_SA);
    float* s_c   = (float*)(smem + SMO_SC);
    float* sS    = (float*)(smem + SMO_SS);
    float* sQ    = (float*)(smem + SMO_SQ);

    int tid = threadIdx.x, wid = tid >> 5, lane = tid & 31;
    int wr = wid >> 2;        // 0..1 : rows wr*32 .. +32
    int wc = wid & 3;         // 0..3 : cols wc*32 .. +32
    int gid = lane >> 2;      // 0..7
    int tig = lane & 3;       // 0..3

    // ---- once per CTA: bias, BN1 affine, W tile ----
    if (tid < 128) {
        sbias[tid] = bias[tid];
        if (BN1) {
            float mu  = g_stats[tid] * invN;
            float var = g_stats[128 + tid] * invN - mu * mu;
            float a = gamma[tid] * rsqrtf(var + 1e-5f);
            s_a[tid] = a;
            s_c[tid] = beta[tid] - mu * a;
        }
    }
#pragma unroll
    for (int it = 0; it < 8; ++it) {
        int idx = tid + it * 256;            // 0..2047
        int row = idx >> 4;                  // 0..127
        int c   = idx & 15;
        uint4 h = *(const uint4*)(Wh + (size_t)row * 64 + c * 4);
        uint4 l = *(const uint4*)(Wl + (size_t)row * 64 + c * 4);
        int o = row * ROWW + c * 4;
        *(uint4*)(Bh + o) = h;
        *(uint4*)(Bl + o) = l;
    }

    // ---- persistent tile loop ----
    for (int t = blockIdx.x; t < tiles; t += gridDim.x) {
        int m0 = t * 64;
        if (tid < 128) { sS[tid] = 0.f; sQ[tid] = 0.f; }

        // ---- A tile (64 rows) ----
        if (BN1) {
            // need affine ready on the FIRST iteration: covered by the
            // __syncthreads below (writes above happen before it).
#pragma unroll
            for (int it = 0; it < 8; ++it) {
                int idx = tid + it * 256;        // 0..2047
                int row = idx >> 5;              // 0..63
                int kq  = idx & 31;              // float4 index 0..31
                int gm = m0 + row; if (gm >= N) gm = N - 1;
                float4 v = *(const float4*)(g_h1 + (size_t)gm * 128 + kq * 4);
                // NOTE: s_a/s_c written by tid<128 before first sync; on the
                // first tile these reads race ONLY within this thread's own
                // pre-sync window. Guard: use values loaded after syncthreads
                // by deferring the fold to post-sync? Instead we sync first.
                int o = row * ROWW + kq * 2;
                // stash raw floats temporarily in Ah/Al as bit patterns
                *(uint2*)(Ah + o) = make_uint2(__float_as_uint(v.x),
                                               __float_as_uint(v.z));
                *(uint2*)(Al + o) = make_uint2(__float_as_uint(v.y),
                                               __float_as_uint(v.w));
            }
            __syncthreads();   // raw A staged; s_a/s_c & W ready
            // fold BN1+ReLU and split in place
#pragma unroll
            for (int it = 0; it < 8; ++it) {
                int idx = tid + it * 256;
                int row = idx >> 5;
                int kq  = idx & 31;
                int o = row * ROWW + kq * 2;
                uint2 rh = *(uint2*)(Ah + o);
                uint2 rl = *(uint2*)(Al + o);
                float vx = __uint_as_float(rh.x);
                float vz = __uint_as_float(rh.y);
                float vy = __uint_as_float(rl.x);
                float vw = __uint_as_float(rl.y);
                int k0 = kq * 4;
                vx = fmaxf(fmaf(vx, s_a[k0 + 0], s_c[k0 + 0]), 0.f);
                vy = fmaxf(fmaf(vy, s_a[k0 + 1], s_c[k0 + 1]), 0.f);
                vz = fmaxf(fmaf(vz, s_a[k0 + 2], s_c[k0 + 2]), 0.f);
                vw = fmaxf(fmaf(vw, s_a[k0 + 3], s_c[k0 + 3]), 0.f);
                uint32_t h0, l0, h1, l1;
                split_h2(vx, vy, h0, l0);
                split_h2(vz, vw, h1, l1);
                *(uint2*)(Ah + o) = make_uint2(h0, h1);
                *(uint2*)(Al + o) = make_uint2(l0, l1);
            }
        } else {
            // pure copy of pre-split agg: 64 rows x 16 uint4 -> 4 iters
#pragma unroll
            for (int it = 0; it < 4; ++it) {
                int idx = tid + it * 256;        // 0..1023
                int row = idx >> 4;              // 0..63
                int c   = idx & 15;              // uint4 index 0..15
                int gm = m0 + row; if (gm >= N) gm = N - 1;
                uint4 h = *(const uint4*)(g_aggh + (size_t)gm * 64 + c * 4);
                uint4 l = *(const uint4*)(g_aggl + (size_t)gm * 64 + c * 4);
                int o = row * ROWW + c * 4;
                *(uint4*)(Ah + o) = h;
                *(uint4*)(Al + o) = l;
            }
        }
        __syncthreads();

        // ---- mainloop: 8 K-chunks of 16; warp tile 32x32 ----
        float acc[2][4][4];
#pragma unroll
        for (int mt = 0; mt < 2; ++mt)
#pragma unroll
            for (int nt = 0; nt < 4; ++nt)
#pragma unroll
                for (int r = 0; r < 4; ++r) acc[mt][nt][r] = 0.f;

#pragma unroll
        for (int ks = 0; ks < 8; ++ks) {
            int kw0 = ks * 8;
            uint32_t ahi[2][4], alo[2][4];
#pragma unroll
            for (int mt = 0; mt < 2; ++mt) {
                int r0 = wr * 32 + mt * 16 + gid;
                ahi[mt][0] = Ah[r0 * ROWW + kw0 + tig];
                ahi[mt][1] = Ah[(r0 + 8) * ROWW + kw0 + tig];
                ahi[mt][2] = Ah[r0 * ROWW + kw0 + tig + 4];
                ahi[mt][3] = Ah[(r0 + 8) * ROWW + kw0 + tig + 4];
                alo[mt][0] = Al[r0 * ROWW + kw0 + tig];
                alo[mt][1] = Al[(r0 + 8) * ROWW + kw0 + tig];
                alo[mt][2] = Al[r0 * ROWW + kw0 + tig + 4];
                alo[mt][3] = Al[(r0 + 8) * ROWW + kw0 + tig + 4];
            }
#pragma unroll
            for (int nt = 0; nt < 4; ++nt) {
                int n = wc * 32 + nt * 8 + gid;
                uint32_t bh0 = Bh[n * ROWW + kw0 + tig];
                uint32_t bh1 = Bh[n * ROWW + kw0 + tig + 4];
                uint32_t bl0 = Bl[n * ROWW + kw0 + tig];
                uint32_t bl1 = Bl[n * ROWW + kw0 + tig + 4];
#pragma unroll
                for (int mt = 0; mt < 2; ++mt) {
                    mma_f16(acc[mt][nt], ahi[mt], bh0, bh1);
                    mma_f16(acc[mt][nt], ahi[mt], bl0, bl1);
                    mma_f16(acc[mt][nt], alo[mt], bh0, bh1);
                }
            }
        }

        // ---- epilogue: bias add, store, fused column stats ----
        float ls[8], lq[8];
#pragma unroll
        for (int i = 0; i < 8; ++i) { ls[i] = 0.f; lq[i] = 0.f; }

#pragma unroll
        for (int mt = 0; mt < 2; ++mt) {
            int grow0 = m0 + wr * 32 + mt * 16 + gid;
            int grow1 = grow0 + 8;
            bool v0 = grow0 < N, v1 = grow1 < N;
#pragma unroll
            for (int nt = 0; nt < 4; ++nt) {
                int gcol = wc * 32 + nt * 8 + tig * 2;
                float d0 = acc[mt][nt][0] + sbias[gcol];
                float d1 = acc[mt][nt][1] + sbias[gcol + 1];
                float d2 = acc[mt][nt][2] + sbias[gcol];
                float d3 = acc[mt][nt][3] + sbias[gcol + 1];
                if (v0) {
                    *(float2*)(C + (size_t)grow0 * 128 + gcol) = make_float2(d0, d1);
                    ls[nt * 2]     += d0; lq[nt * 2]     = fmaf(d0, d0, lq[nt * 2]);
                    ls[nt * 2 + 1] += d1; lq[nt * 2 + 1] = fmaf(d1, d1, lq[nt * 2 + 1]);
                }
                if (v1) {
                    *(float2*)(C + (size_t)grow1 * 128 + gcol) = make_float2(d2, d3);
                    ls[nt * 2]     += d2; lq[nt * 2]     = fmaf(d2, d2, lq[nt * 2]);
                    ls[nt * 2 + 1] += d3; lq[nt * 2 + 1] = fmaf(d3, d3, lq[nt * 2 + 1]);
                }
            }
        }
#pragma unroll
        for (int d = 4; d < 32; d <<= 1) {
#pragma unroll
            for (int i = 0; i < 8; ++i) {
                ls[i] += __shfl_xor_sync(0xFFFFFFFFu, ls[i], d);
                lq[i] += __shfl_xor_sync(0xFFFFFFFFu, lq[i], d);
            }
        }
        if (gid == 0) {
#pragma unroll
            for (int i = 0; i < 8; ++i) {
                int col = wc * 32 + (i >> 1) * 8 + tig * 2 + (i & 1);
                atomicAdd(&sS[col], ls[i]);
                atomicAdd(&sQ[col], lq[i]);
            }
        }
        __syncthreads();
        if (tid < 128) {
            atomicAdd(&statSum[tid], sS[tid]);
            atomicAdd(&statSq[tid],  sQ[tid]);
        }
    }
}

// out = relu(BN2(out)), BN2 affine computed per block from g_stats.
__global__ void __launch_bounds__(256)
bnrelu_kernel(float* __restrict__ out,
              const float* __restrict__ gamma, const float* __restrict__ beta,
              int N, float invN) {
    __shared__ float s_a[128], s_c[128];
    int tid = threadIdx.x;
    if (tid < 128) {
        float mu  = g_stats[256 + tid] * invN;
        float var = g_stats[384 + tid] * invN - mu * mu;
        float a = gamma[tid] * rsqrtf(var + 1e-5f);
        s_a[tid] = a;
        s_c[tid] = beta[tid] - mu * a;
    }
    __syncthreads();
    int c4 = (tid & 31) << 2;
    float4 a4  = *(const float4*)(s_a + c4);
    float4 c4v = *(const float4*)(s_c + c4);
    int rows_per_iter = gridDim.x * (blockDim.x >> 5);
    int r = blockIdx.x * (blockDim.x >> 5) + (tid >> 5);
    float4* o4 = (float4*)out;
    for (; r < N; r += rows_per_iter) {
        size_t idx = (size_t)r * 32 + (tid & 31);
        float4 v = o4[idx];
        v.x = fmaxf(fmaf(v.x, a4.x, c4v.x), 0.f);
        v.y = fmaxf(fmaf(v.y, a4.y, c4v.y), 0.f);
        v.z = fmaxf(fmaf(v.z, a4.z, c4v.z), 0.f);
        v.w = fmaxf(fmaf(v.w, a4.w, c4v.w), 0.f);
        o4[idx] = v;
    }
}

// ---------------------------------------------------------------------------
extern "C" void kernel_launch(void* const* d_in, const int* in_sizes, int n_in,
                              void* d_out, int out_size) {
    const float* x   = (const float*)d_in[0];
    const void*  ei  = d_in[1];
    const float* eps = (const float*)d_in[2];
    const float* W1  = (const float*)d_in[3];
    const float* b1  = (const float*)d_in[4];
    const float* g1  = (const float*)d_in[5];
    const float* be1 = (const float*)d_in[6];
    const float* W2  = (const float*)d_in[7];
    const float* b2  = (const float*)d_in[8];
    const float* g2  = (const float*)d_in[9];
    const float* be2 = (const float*)d_in[10];

    int N = in_sizes[0] / 128;
    int E = in_sizes[1] / 2;
    if (E > MAXE) E = MAXE;
    float* out = (float*)d_out;
    float invN = 1.f / (float)N;
    int tiles = (N + 63) / 64;

    cudaFuncSetAttribute(gemm_mma<false>,
                         cudaFuncAttributeMaxDynamicSharedMemorySize, SMEM_GEMM);
    cudaFuncSetAttribute(gemm_mma<true>,
                         cudaFuncAttributeMaxDynamicSharedMemorySize, SMEM_GEMM);

    init_kernel<<<(N + 255) / 256, 256>>>((const int*)ei, E, N);
    wsplit_kernel<<<32, 256>>>(W1, W2);
    bucket_kernel<<<(E + 511) / 512, 256>>>(ei, E);

    int ablocks = (N * 32 + 255) / 256;
    aggregate_kernel<<<ablocks, 256>>>(x, eps, N);

    int gblocks = tiles < 296 ? tiles : 296;   // 2 CTAs/SM, persistent
    gemm_mma<false><<<gblocks, 256, SMEM_GEMM>>>(b1, nullptr, nullptr,
                                                 nullptr, N, invN, tiles);
    gemm_mma<true><<<gblocks, 256, SMEM_GEMM>>>(b2, g1, be1, out, N, invN,
                                                tiles);
    bnrelu_kernel<<<592, 256>>>(out, g2, be2, N, invN);
}

// round 17
// speedup vs baseline: 1.2664x; 1.0176x over previous
#include <cuda_runtime.h>
#include <cuda_fp16.h>
#include <cstdint>

// ---------------------------------------------------------------------------
// GIN block. 7-kernel pipeline (bucket CSR; W/agg pre-split; persistent GEMM
// with register-staged A double-buffering):
//   init -> wsplit -> bucket -> aggregate (gather, writes fp16 hi/lo) ->
//   gemm1 (persistent, W resident, A prefetch in regs, fused BN1 stats) ->
//   gemm2 (persistent, BN1 fold+split from reg prefetch, fused BN2 stats) ->
//   bnrelu.
// R16 lesson: persistent CTAs won; remaining GEMM wall = serialized
// A-fill vs MMA -> overlap via register prefetch of next tile.
// Aggregate measured AT the LTS gather roofline (~33us) - algorithm stays.
// ---------------------------------------------------------------------------

#define MAXN 50048
#define MAXE 1600000
#define BK   64         // bucket slots per node (Poisson(16) max deg ~40)

__device__ __align__(16) uint32_t g_aggh[MAXN * 64];  // fp16x2 hi words
__device__ __align__(16) uint32_t g_aggl[MAXN * 64];  // fp16x2 lo words
__device__ __align__(16) float    g_h1[MAXN * 128];
__device__ __align__(16) uint32_t g_w1h[128 * 64], g_w1l[128 * 64];
__device__ __align__(16) uint32_t g_w2h[128 * 64], g_w2l[128 * 64];
__device__ float g_stats[512];   // [sum1, sumsq1, sum2, sumsq2] x 128
__device__ int   g_deg[MAXN];
__device__ int   g_bucket[MAXN * BK];
__device__ int   g_ovf[2 * MAXE];  // (dst, src) pairs for rank >= BK
__device__ int   g_ovfcnt;
__device__ int   g_is64;

__device__ __forceinline__ void split_h2(float x, float y,
                                         uint32_t& hi, uint32_t& lo) {
    __half hx = __float2half_rn(x), hy = __float2half_rn(y);
    __half lx = __float2half_rn(x - __half2float(hx));
    __half ly = __float2half_rn(y - __half2float(hy));
    hi = (uint32_t)__half_as_ushort(hx) | ((uint32_t)__half_as_ushort(hy) << 16);
    lo = (uint32_t)__half_as_ushort(lx) | ((uint32_t)__half_as_ushort(ly) << 16);
}

// ---------------------------------------------------------------------------
__global__ void init_kernel(const int* __restrict__ ei32, int E, int N) {
    int i = blockIdx.x * blockDim.x + threadIdx.x;
    if (i < N) g_deg[i] = 0;
    if (i < 512) g_stats[i] = 0.f;
    if (i == 0) g_ovfcnt = 0;
    if (blockIdx.x == 0) {
        __shared__ int nz;
        if (threadIdx.x == 0) nz = 0;
        __syncthreads();
        int pairs = E < 2048 ? E : 2048;
        int cnt = 0;
        for (int j = threadIdx.x; j < pairs; j += blockDim.x)
            if (ei32[2 * j + 1] != 0) cnt++;
        if (cnt) atomicOr(&nz, 1);
        __syncthreads();
        if (threadIdx.x == 0) g_is64 = (nz == 0) ? 1 : 0;
    }
}

// Split W1 and W2 (16384 floats each) into fp16 hi/lo word arrays, once.
__global__ void wsplit_kernel(const float* __restrict__ W1,
                              const float* __restrict__ W2) {
    int i = blockIdx.x * blockDim.x + threadIdx.x;  // 0..8191 (float4 units)
    int m = i >> 12;                                 // 0: W1, 1: W2
    int j = i & 4095;                                // float4 index in matrix
    const float* W = m ? W2 : W1;
    uint32_t* Hh = m ? g_w2h : g_w1h;
    uint32_t* Hl = m ? g_w2l : g_w1l;
    float4 v = ((const float4*)W)[j];
    uint32_t h0, l0, h1, l1;
    split_h2(v.x, v.y, h0, l0);
    split_h2(v.z, v.w, h1, l1);
    ((uint2*)Hh)[j] = make_uint2(h0, h1);
    ((uint2*)Hl)[j] = make_uint2(l0, l1);
}

__device__ __forceinline__ int load_idx(const void* ei, long long i) {
    return g_is64 ? (int)((const long long*)ei)[i] : ((const int*)ei)[i];
}

// Histogram + direct bucket write. 2 edges per thread.
__global__ void bucket_kernel(const void* __restrict__ ei, int E) {
    int i = (blockIdx.x * blockDim.x + threadIdx.x) * 2;
#pragma unroll
    for (int t = 0; t < 2; ++t, ++i) {
        if (i >= E) return;
        int src = load_idx(ei, i);
        int dst = load_idx(ei, (long long)E + i);
        int r = atomicAdd(&g_deg[dst], 1);
        if (r < BK) {
            g_bucket[dst * BK + r] = src;
        } else {
            int o = atomicAdd(&g_ovfcnt, 1);
            g_ovf[2 * o] = dst;
            g_ovf[2 * o + 1] = src;
        }
    }
}

// One warp per node: acc = (1+eps)*x[node] + sum of bucketed neighbor rows.
__global__ void aggregate_kernel(const float* __restrict__ x,
                                 const float* __restrict__ eps, int N) {
    int w = (int)((blockIdx.x * blockDim.x + threadIdx.x) >> 5);
    if (w >= N) return;
    int lane = threadIdx.x & 31;
    const float4* x4 = (const float4*)x;
    float s = 1.f + eps[0];
    float4 acc = x4[(size_t)w * 32 + lane];
    acc.x *= s; acc.y *= s; acc.z *= s; acc.w *= s;
    float4 acc2 = make_float4(0.f, 0.f, 0.f, 0.f);
    int deg = g_deg[w];
    int cnt = deg < BK ? deg : BK;
    const int* bk = g_bucket + (size_t)w * BK;
    int j = 0;
    for (; j + 3 < cnt; j += 4) {
        int4 si = *(const int4*)(bk + j);
        float4 v0 = x4[(size_t)si.x * 32 + lane];
        float4 v1 = x4[(size_t)si.y * 32 + lane];
        float4 v2 = x4[(size_t)si.z * 32 + lane];
        float4 v3 = x4[(size_t)si.w * 32 + lane];
        acc.x  += v0.x + v1.x; acc.y  += v0.y + v1.y;
        acc.z  += v0.z + v1.z; acc.w  += v0.w + v1.w;
        acc2.x += v2.x + v3.x; acc2.y += v2.y + v3.y;
        acc2.z += v2.z + v3.z; acc2.w += v2.w + v3.w;
    }
    for (; j < cnt; j++) {
        float4 v0 = x4[(size_t)bk[j] * 32 + lane];
        acc.x += v0.x; acc.y += v0.y; acc.z += v0.z; acc.w += v0.w;
    }
    if (deg > BK) {  // drain overflow entries for this node (rare/none)
        int oc = g_ovfcnt;
        for (int i = 0; i < oc; ++i) {
            if (g_ovf[2 * i] == w) {
                float4 v0 = x4[(size_t)g_ovf[2 * i + 1] * 32 + lane];
                acc.x += v0.x; acc.y += v0.y; acc.z += v0.z; acc.w += v0.w;
            }
        }
    }
    acc.x += acc2.x; acc.y += acc2.y; acc.z += acc2.z; acc.w += acc2.w;
    uint32_t h0, l0, h1, l1;
    split_h2(acc.x, acc.y, h0, l0);
    split_h2(acc.z, acc.w, h1, l1);
    ((uint2*)g_aggh)[(size_t)w * 32 + lane] = make_uint2(h0, h1);
    ((uint2*)g_aggl)[(size_t)w * 32 + lane] = make_uint2(l0, l1);
}

// ---------------------------------------------------------------------------
// Persistent 3xFP16-split tensor-core GEMM (m16n8k16): D = Ain @ W^T + bias.
// Grid 296 = 2 CTAs/SM. W/bias/affine loaded once per CTA. A tile for the
// NEXT iteration is prefetched into registers while the current tile's MMA
// and epilogue run (register-staged double buffer).
// gemm1: A = pre-split agg. gemm2: A = relu(BN1(g_h1)) folded+split on stage.
// ---------------------------------------------------------------------------
#define ROWW 68                          // words per row (64 + 4 pad)
#define SMO_AH   0                       // 64*68*4   = 17408
#define SMO_AL   17408                   // +17408    = 34816
#define SMO_BH   34816                   // 128*68*4  = 34816 -> 69632
#define SMO_BL   69632                   // +34816    = 104448
#define SMO_BIAS 104448
#define SMO_SA   (SMO_BIAS + 512)
#define SMO_SC   (SMO_SA + 512)
#define SMO_SS   (SMO_SC + 512)
#define SMO_SQ   (SMO_SS + 512)
#define SMEM_GEMM (SMO_SQ + 512)         // 107008 bytes -> 2 CTAs/SM

__device__ __forceinline__ void mma_f16(float* d, const uint32_t* a,
                                        uint32_t b0, uint32_t b1) {
    asm volatile(
        "mma.sync.aligned.m16n8k16.row.col.f32.f16.f16.f32 "
        "{%0,%1,%2,%3}, {%4,%5,%6,%7}, {%8,%9}, {%0,%1,%2,%3};"
        : "+f"(d[0]), "+f"(d[1]), "+f"(d[2]), "+f"(d[3])
        : "r"(a[0]), "r"(a[1]), "r"(a[2]), "r"(a[3]), "r"(b0), "r"(b1));
}

template <bool BN1>
__global__ void __launch_bounds__(256, 2)
gemm_mma(const float* __restrict__ bias,
         const float* __restrict__ gamma, const float* __restrict__ beta,
         float* __restrict__ outp, int N, float invN, int tiles) {
    float* C        = BN1 ? outp : g_h1;
    float* statSum  = BN1 ? (g_stats + 256) : g_stats;
    float* statSq   = BN1 ? (g_stats + 384) : (g_stats + 128);
    const uint32_t* Wh = BN1 ? g_w2h : g_w1h;
    const uint32_t* Wl = BN1 ? g_w2l : g_w1l;

    extern __shared__ __align__(16) char smem[];
    uint32_t* Ah = (uint32_t*)(smem + SMO_AH);
    uint32_t* Al = (uint32_t*)(smem + SMO_AL);
    uint32_t* Bh = (uint32_t*)(smem + SMO_BH);
    uint32_t* Bl = (uint32_t*)(smem + SMO_BL);
    float* sbias = (float*)(smem + SMO_BIAS);
    float* s_a   = (float*)(smem + SMO_SA);
    float* s_c   = (float*)(smem + SMO_SC);
    float* sS    = (float*)(smem + SMO_SS);
    float* sQ    = (float*)(smem + SMO_SQ);

    int tid = threadIdx.x, wid = tid >> 5, lane = tid & 31;
    int wr = wid >> 2;        // 0..1 : rows wr*32 .. +32
    int wc = wid & 3;         // 0..3 : cols wc*32 .. +32
    int gid = lane >> 2;      // 0..7
    int tig = lane & 3;       // 0..3

    // ---- once per CTA: bias, BN1 affine, W tile ----
    if (tid < 128) {
        sbias[tid] = bias[tid];
        if (BN1) {
            float mu  = g_stats[tid] * invN;
            float var = g_stats[128 + tid] * invN - mu * mu;
            float a = gamma[tid] * rsqrtf(var + 1e-5f);
            s_a[tid] = a;
            s_c[tid] = beta[tid] - mu * a;
        }
    }
#pragma unroll
    for (int it = 0; it < 8; ++it) {
        int idx = tid + it * 256;            // 0..2047
        int row = idx >> 4;                  // 0..127
        int c   = idx & 15;
        uint4 h = *(const uint4*)(Wh + (size_t)row * 64 + c * 4);
        uint4 l = *(const uint4*)(Wl + (size_t)row * 64 + c * 4);
        int o = row * ROWW + c * 4;
        *(uint4*)(Bh + o) = h;
        *(uint4*)(Bl + o) = l;
    }

    // Per-thread A-prefetch registers.
    // gemm1: 4 x (uint4 hi + uint4 lo).  gemm2: 8 x float4 raw fp32.
    uint4 ph[4], pl[4];
    float4 pf[8];

    // ---- prefetch first tile ----
    int t = blockIdx.x;
    if (t < tiles) {
        int m0 = t * 64;
        if (BN1) {
#pragma unroll
            for (int it = 0; it < 8; ++it) {
                int idx = tid + it * 256;        // 0..2047
                int row = idx >> 5;              // 0..63
                int kq  = idx & 31;              // float4 index
                int gm = m0 + row; if (gm >= N) gm = N - 1;
                pf[it] = *(const float4*)(g_h1 + (size_t)gm * 128 + kq * 4);
            }
        } else {
#pragma unroll
            for (int it = 0; it < 4; ++it) {
                int idx = tid + it * 256;        // 0..1023
                int row = idx >> 4;              // 0..63
                int c   = idx & 15;
                int gm = m0 + row; if (gm >= N) gm = N - 1;
                ph[it] = *(const uint4*)(g_aggh + (size_t)gm * 64 + c * 4);
                pl[it] = *(const uint4*)(g_aggl + (size_t)gm * 64 + c * 4);
            }
        }
    }

    // ---- persistent tile loop ----
    for (; t < tiles; t += gridDim.x) {
        int m0 = t * 64;
        __syncthreads();   // previous tile's MMA done; A smem free; s_a ready
        if (tid < 128) { sS[tid] = 0.f; sQ[tid] = 0.f; }

        // ---- stage prefetched A into smem (fold+split for gemm2) ----
        if (BN1) {
#pragma unroll
            for (int it = 0; it < 8; ++it) {
                int idx = tid + it * 256;
                int row = idx >> 5;
                int kq  = idx & 31;
                int k0 = kq * 4;
                float vx = fmaxf(fmaf(pf[it].x, s_a[k0 + 0], s_c[k0 + 0]), 0.f);
                float vy = fmaxf(fmaf(pf[it].y, s_a[k0 + 1], s_c[k0 + 1]), 0.f);
                float vz = fmaxf(fmaf(pf[it].z, s_a[k0 + 2], s_c[k0 + 2]), 0.f);
                float vw = fmaxf(fmaf(pf[it].w, s_a[k0 + 3], s_c[k0 + 3]), 0.f);
                uint32_t h0, l0, h1, l1;
                split_h2(vx, vy, h0, l0);
                split_h2(vz, vw, h1, l1);
                int o = row * ROWW + kq * 2;
                *(uint2*)(Ah + o) = make_uint2(h0, h1);
                *(uint2*)(Al + o) = make_uint2(l0, l1);
            }
        } else {
#pragma unroll
            for (int it = 0; it < 4; ++it) {
                int idx = tid + it * 256;
                int row = idx >> 4;
                int c   = idx & 15;
                int o = row * ROWW + c * 4;
                *(uint4*)(Ah + o) = ph[it];
                *(uint4*)(Al + o) = pl[it];
            }
        }

        // ---- prefetch NEXT tile (overlaps with this tile's MMA/epilogue) ----
        int tn = t + gridDim.x;
        if (tn < tiles) {
            int mn = tn * 64;
            if (BN1) {
#pragma unroll
                for (int it = 0; it < 8; ++it) {
                    int idx = tid + it * 256;
                    int row = idx >> 5;
                    int kq  = idx & 31;
                    int gm = mn + row; if (gm >= N) gm = N - 1;
                    pf[it] = *(const float4*)(g_h1 + (size_t)gm * 128 + kq * 4);
                }
            } else {
#pragma unroll
                for (int it = 0; it < 4; ++it) {
                    int idx = tid + it * 256;
                    int row = idx >> 4;
                    int c   = idx & 15;
                    int gm = mn + row; if (gm >= N) gm = N - 1;
                    ph[it] = *(const uint4*)(g_aggh + (size_t)gm * 64 + c * 4);
                    pl[it] = *(const uint4*)(g_aggl + (size_t)gm * 64 + c * 4);
                }
            }
        }
        __syncthreads();   // A smem + stats zeroed, ready for MMA

        // ---- mainloop: 8 K-chunks of 16; warp tile 32x32 ----
        float acc[2][4][4];
#pragma unroll
        for (int mt = 0; mt < 2; ++mt)
#pragma unroll
            for (int nt = 0; nt < 4; ++nt)
#pragma unroll
                for (int r = 0; r < 4; ++r) acc[mt][nt][r] = 0.f;

#pragma unroll
        for (int ks = 0; ks < 8; ++ks) {
            int kw0 = ks * 8;
            uint32_t ahi[2][4], alo[2][4];
#pragma unroll
            for (int mt = 0; mt < 2; ++mt) {
                int r0 = wr * 32 + mt * 16 + gid;
                ahi[mt][0] = Ah[r0 * ROWW + kw0 + tig];
                ahi[mt][1] = Ah[(r0 + 8) * ROWW + kw0 + tig];
                ahi[mt][2] = Ah[r0 * ROWW + kw0 + tig + 4];
                ahi[mt][3] = Ah[(r0 + 8) * ROWW + kw0 + tig + 4];
                alo[mt][0] = Al[r0 * ROWW + kw0 + tig];
                alo[mt][1] = Al[(r0 + 8) * ROWW + kw0 + tig];
                alo[mt][2] = Al[r0 * ROWW + kw0 + tig + 4];
                alo[mt][3] = Al[(r0 + 8) * ROWW + kw0 + tig + 4];
            }
#pragma unroll
            for (int nt = 0; nt < 4; ++nt) {
                int n = wc * 32 + nt * 8 + gid;
                uint32_t bh0 = Bh[n * ROWW + kw0 + tig];
                uint32_t bh1 = Bh[n * ROWW + kw0 + tig + 4];
                uint32_t bl0 = Bl[n * ROWW + kw0 + tig];
                uint32_t bl1 = Bl[n * ROWW + kw0 + tig + 4];
#pragma unroll
                for (int mt = 0; mt < 2; ++mt) {
                    mma_f16(acc[mt][nt], ahi[mt], bh0, bh1);
                    mma_f16(acc[mt][nt], ahi[mt], bl0, bl1);
                    mma_f16(acc[mt][nt], alo[mt], bh0, bh1);
                }
            }
        }

        // ---- epilogue: bias add, store, fused column stats ----
        float ls[8], lq[8];
#pragma unroll
        for (int i = 0; i < 8; ++i) { ls[i] = 0.f; lq[i] = 0.f; }

#pragma unroll
        for (int mt = 0; mt < 2; ++mt) {
            int grow0 = m0 + wr * 32 + mt * 16 + gid;
            int grow1 = grow0 + 8;
            bool v0 = grow0 < N, v1 = grow1 < N;
#pragma unroll
            for (int nt = 0; nt < 4; ++nt) {
                int gcol = wc * 32 + nt * 8 + tig * 2;
                float d0 = acc[mt][nt][0] + sbias[gcol];
                float d1 = acc[mt][nt][1] + sbias[gcol + 1];
                float d2 = acc[mt][nt][2] + sbias[gcol];
                float d3 = acc[mt][nt][3] + sbias[gcol + 1];
                if (v0) {
                    *(float2*)(C + (size_t)grow0 * 128 + gcol) = make_float2(d0, d1);
                    ls[nt * 2]     += d0; lq[nt * 2]     = fmaf(d0, d0, lq[nt * 2]);
                    ls[nt * 2 + 1] += d1; lq[nt * 2 + 1] = fmaf(d1, d1, lq[nt * 2 + 1]);
                }
                if (v1) {
                    *(float2*)(C + (size_t)grow1 * 128 + gcol) = make_float2(d2, d3);
                    ls[nt * 2]     += d2; lq[nt * 2]     = fmaf(d2, d2, lq[nt * 2]);
                    ls[nt * 2 + 1] += d3; lq[nt * 2 + 1] = fmaf(d3, d3, lq[nt * 2 + 1]);
                }
            }
        }
#pragma unroll
        for (int d = 4; d < 32; d <<= 1) {
#pragma unroll
            for (int i = 0; i < 8; ++i) {
                ls[i] += __shfl_xor_sync(0xFFFFFFFFu, ls[i], d);
                lq[i] += __shfl_xor_sync(0xFFFFFFFFu, lq[i], d);
            }
        }
        if (gid == 0) {
#pragma unroll
            for (int i = 0; i < 8; ++i) {
                int col = wc * 32 + (i >> 1) * 8 + tig * 2 + (i & 1);
                atomicAdd(&sS[col], ls[i]);
                atomicAdd(&sQ[col], lq[i]);
            }
        }
        __syncthreads();
        if (tid < 128) {
            atomicAdd(&statSum[tid], sS[tid]);
            atomicAdd(&statSq[tid],  sQ[tid]);
        }
    }
}

// out = relu(BN2(out)), BN2 affine computed per block from g_stats.
__global__ void __launch_bounds__(256)
bnrelu_kernel(float* __restrict__ out,
              const float* __restrict__ gamma, const float* __restrict__ beta,
              int N, float invN) {
    __shared__ float s_a[128], s_c[128];
    int tid = threadIdx.x;
    if (tid < 128) {
        float mu  = g_stats[256 + tid] * invN;
        float var = g_stats[384 + tid] * invN - mu * mu;
        float a = gamma[tid] * rsqrtf(var + 1e-5f);
        s_a[tid] = a;
        s_c[tid] = beta[tid] - mu * a;
    }
    __syncthreads();
    int c4 = (tid & 31) << 2;
    float4 a4  = *(const float4*)(s_a + c4);
    float4 c4v = *(const float4*)(s_c + c4);
    int rows_per_iter = gridDim.x * (blockDim.x >> 5);
    int r = blockIdx.x * (blockDim.x >> 5) + (tid >> 5);
    float4* o4 = (float4*)out;
    for (; r < N; r += rows_per_iter) {
        size_t idx = (size_t)r * 32 + (tid & 31);
        float4 v = o4[idx];
        v.x = fmaxf(fmaf(v.x, a4.x, c4v.x), 0.f);
        v.y = fmaxf(fmaf(v.y, a4.y, c4v.y), 0.f);
        v.z = fmaxf(fmaf(v.z, a4.z, c4v.z), 0.f);
        v.w = fmaxf(fmaf(v.w, a4.w, c4v.w), 0.f);
        o4[idx] = v;
    }
}

// ---------------------------------------------------------------------------
extern "C" void kernel_launch(void* const* d_in, const int* in_sizes, int n_in,
                              void* d_out, int out_size) {
    const float* x   = (const float*)d_in[0];
    const void*  ei  = d_in[1];
    const float* eps = (const float*)d_in[2];
    const float* W1  = (const float*)d_in[3];
    const float* b1  = (const float*)d_in[4];
    const float* g1  = (const float*)d_in[5];
    const float* be1 = (const float*)d_in[6];
    const float* W2  = (const float*)d_in[7];
    const float* b2  = (const float*)d_in[8];
    const float* g2  = (const float*)d_in[9];
    const float* be2 = (const float*)d_in[10];

    int N = in_sizes[0] / 128;
    int E = in_sizes[1] / 2;
    if (E > MAXE) E = MAXE;
    float* out = (float*)d_out;
    float invN = 1.f / (float)N;
    int tiles = (N + 63) / 64;

    cudaFuncSetAttribute(gemm_mma<false>,
                         cudaFuncAttributeMaxDynamicSharedMemorySize, SMEM_GEMM);
    cudaFuncSetAttribute(gemm_mma<true>,
                         cudaFuncAttributeMaxDynamicSharedMemorySize, SMEM_GEMM);

    init_kernel<<<(N + 255) / 256, 256>>>((const int*)ei, E, N);
    wsplit_kernel<<<32, 256>>>(W1, W2);
    bucket_kernel<<<(E + 511) / 512, 256>>>(ei, E);

    int ablocks = (N * 32 + 255) / 256;
    aggregate_kernel<<<ablocks, 256>>>(x, eps, N);

    int gblocks = tiles < 296 ? tiles : 296;   // 2 CTAs/SM, persistent
    gemm_mma<false><<<gblocks, 256, SMEM_GEMM>>>(b1, nullptr, nullptr,
                                                 nullptr, N, invN, tiles);
    gemm_mma<true><<<gblocks, 256, SMEM_GEMM>>>(b2, g1, be1, out, N, invN,
                                                tiles);
    bnrelu_kernel<<<592, 256>>>(out, g2, be2, N, invN);
}